// round 11
// baseline (speedup 1.0000x reference)
#include <cuda_runtime.h>
#include <cuda_fp16.h>
#include <cstdint>

#define NH 16
#define NB 4
#define SQ 1024
#define DM 1024
#define DK 64
#define MR (NB * SQ)
#define HB (NH * NB)

// fp16 scratch (__device__ globals per allocation-free rule)
__device__ __half g_xq[(size_t)MR * DM];
__device__ __half g_xk[(size_t)MR * DM];
__device__ __half g_xv[(size_t)MR * DM];
__device__ __half g_wq[(size_t)NH * DM * DK];
__device__ __half g_wk[(size_t)NH * DM * DK];
__device__ __half g_wv[(size_t)NH * DM * DK];
__device__ __half g_wo[(size_t)DM * DM];
__device__ __half g_qh[(size_t)HB * SQ * DK];
__device__ __half g_kh[(size_t)HB * SQ * DK];
__device__ __half g_vh[(size_t)HB * SQ * DK];
__device__ __half g_ch[(size_t)MR * DM];

__device__ __forceinline__ uint32_t h2u(__half2 h) { return *(uint32_t*)&h; }

__device__ __forceinline__ void ldsm4(uint32_t* r, uint32_t addr) {
    asm volatile("ldmatrix.sync.aligned.m8n8.x4.shared.b16 {%0,%1,%2,%3}, [%4];"
        : "=r"(r[0]), "=r"(r[1]), "=r"(r[2]), "=r"(r[3]) : "r"(addr));
}
__device__ __forceinline__ void ldsm4t(uint32_t* r, uint32_t addr) {
    asm volatile("ldmatrix.sync.aligned.m8n8.x4.trans.shared.b16 {%0,%1,%2,%3}, [%4];"
        : "=r"(r[0]), "=r"(r[1]), "=r"(r[2]), "=r"(r[3]) : "r"(addr));
}
__device__ __forceinline__ void mma16(float* d, const uint32_t* a, const uint32_t* b) {
    asm volatile("mma.sync.aligned.m16n8k16.row.col.f32.f16.f16.f32 "
        "{%0,%1,%2,%3}, {%4,%5,%6,%7}, {%8,%9}, {%0,%1,%2,%3};"
        : "+f"(d[0]), "+f"(d[1]), "+f"(d[2]), "+f"(d[3])
        : "r"(a[0]), "r"(a[1]), "r"(a[2]), "r"(a[3]), "r"(b[0]), "r"(b[1]));
}
__device__ __forceinline__ void cp16(uint32_t dst, const void* src) {
    asm volatile("cp.async.cg.shared.global [%0], [%1], 16;" :: "r"(dst), "l"(src));
}
__device__ __forceinline__ void cp_commit() { asm volatile("cp.async.commit_group;"); }
__device__ __forceinline__ void cp_wait0() { asm volatile("cp.async.wait_group 0;"); }
__device__ __forceinline__ void cp_wait1() { asm volatile("cp.async.wait_group 1;"); }

// ---------------------------------------------------------------------------
// Kernel 0: single fused fp32->fp16 conversion for all 7 input tensors.
// ---------------------------------------------------------------------------
__global__ __launch_bounds__(256) void prep_all(
    const float* __restrict__ q, const float* __restrict__ k, const float* __restrict__ v,
    const float* __restrict__ wq, const float* __restrict__ wk, const float* __restrict__ wv,
    const float* __restrict__ wo)
{
    const int bb = blockIdx.x;
    const float* src; __half* dst; int inner;
    if (bb < 6144) {
        int which = bb >> 11;
        src = (which == 0) ? q : (which == 1) ? k : v;
        dst = (which == 0) ? g_xq : (which == 1) ? g_xk : g_xv;
        inner = bb & 2047;
    } else {
        int which = (bb - 6144) >> 9;
        src = (which == 0) ? wq : (which == 1) ? wk : (which == 2) ? wv : wo;
        dst = (which == 0) ? g_wq : (which == 1) ? g_wk : (which == 2) ? g_wv : g_wo;
        inner = (bb - 6144) & 511;
    }
    size_t i = (size_t)inner * 256 + threadIdx.x;
    float4 a = ((const float4*)src)[i * 2];
    float4 b = ((const float4*)src)[i * 2 + 1];
    uint4 o;
    o.x = h2u(__floats2half2_rn(a.x, a.y));
    o.y = h2u(__floats2half2_rn(a.z, a.w));
    o.z = h2u(__floats2half2_rn(b.x, b.y));
    o.w = h2u(__floats2half2_rn(b.z, b.w));
    ((uint4*)dst)[i] = o;
}

// ---------------------------------------------------------------------------
// Kernel 1: per-head projections. fp16 mma, BK=64, 3-stage cp.async ring,
// depth-2 frag pipeline; first k-step frags loaded BEFORE the prefetch.
// ---------------------------------------------------------------------------
__global__ __launch_bounds__(256, 2) void proj_mma()
{
    const int which = blockIdx.z;
    const __half* X = (which == 0) ? g_xq : (which == 1) ? g_xk : g_xv;
    const __half* W = (which == 0) ? g_wq : (which == 1) ? g_wk : g_wv;
    __half* O       = (which == 0) ? g_qh : (which == 1) ? g_kh : g_vh;
    const int row0 = blockIdx.x * 128;
    const int col0 = blockIdx.y * 128;

    extern __shared__ __align__(16) __half sh[];
    __half* As = sh;                  // [3][128*72]
    __half* Bs = sh + 3 * 128 * 72;   // [3][64*136]
    const uint32_t sA = (uint32_t)__cvta_generic_to_shared(As);
    const uint32_t sB = (uint32_t)__cvta_generic_to_shared(Bs);
    const uint32_t ASZ = 128 * 72 * 2, BSZ = 64 * 136 * 2;

    const int t    = threadIdx.x;
    const int warp = t >> 5, lane = t & 31;
    const int gid  = lane >> 2, tig = lane & 3;
    const int mb   = (warp >> 1) * 32;
    const int nb   = (warp & 1) * 64;
    const int lr   = lane & 15;
    const int lc   = (lane >> 4) * 8;

    uint32_t aoffm[2], boffn[4];
#pragma unroll
    for (int mt = 0; mt < 2; mt++) aoffm[mt] = ((mb + mt * 16 + lr) * 72 + lc) * 2;
#pragma unroll
    for (int p = 0; p < 4; p++) boffn[p] = (lr * 136 + nb + p * 16 + lc) * 2;

    const __half* aptr[4]; uint32_t aoff[4];
    const __half* bptr[4]; uint32_t boff[4];
#pragma unroll
    for (int u = 0; u < 4; u++) {
        int c = t + u * 256;
        int arow = c >> 3, aseg = c & 7;
        aptr[u] = X + (size_t)(row0 + arow) * DM + aseg * 8;
        aoff[u] = (arow * 72 + aseg * 8) * 2;
        int brow = c >> 4, bseg = c & 15;
        int colh = col0 + bseg * 8, hh = colh >> 6, kk = colh & 63;
        bptr[u] = W + (size_t)hh * DM * DK + (size_t)brow * DK + kk;
        boff[u] = (brow * 136 + bseg * 8) * 2;
    }

    float acc[2][8][4] = {};
    const int NT = 16;   // 1024 / 64

#pragma unroll
    for (int p = 0; p < 2; p++) {
#pragma unroll
        for (int u = 0; u < 4; u++) {
            cp16(sA + p * ASZ + aoff[u], aptr[u] + p * 64);
            cp16(sB + p * BSZ + boff[u], bptr[u] + (size_t)(p * 64) * DK);
        }
        cp_commit();
    }

    int slot = 0;
    for (int tt = 0; tt < NT; tt++) {
        cp_wait1();
        __syncthreads();

        const uint32_t sAs = sA + slot * ASZ;
        const uint32_t sBs = sB + slot * BSZ;

        // load first k-step frags immediately (feed tensor pipe asap)
        uint32_t a[2][2][4], b[2][8][2];
#pragma unroll
        for (int mt = 0; mt < 2; mt++) ldsm4(a[0][mt], sAs + aoffm[mt]);
#pragma unroll
        for (int p = 0; p < 4; p++) {
            uint32_t r[4];
            ldsm4t(r, sBs + boffn[p]);
            b[0][p * 2][0] = r[0]; b[0][p * 2][1] = r[1];
            b[0][p * 2 + 1][0] = r[2]; b[0][p * 2 + 1][1] = r[3];
        }

        // prefetch tile tt+2 (slot consumed at tt-1 is free post-barrier)
        if (tt + 2 < NT) {
            const int ps = (tt + 2) % 3;
            const int kt = (tt + 2) * 64;
#pragma unroll
            for (int u = 0; u < 4; u++) {
                cp16(sA + ps * ASZ + aoff[u], aptr[u] + kt);
                cp16(sB + ps * BSZ + boff[u], bptr[u] + (size_t)kt * DK);
            }
        }
        cp_commit();

#pragma unroll
        for (int ks = 0; ks < 4; ks++) {
            const int cur = ks & 1, nxt = cur ^ 1;
            if (ks < 3) {
                const int ko = (ks + 1) * 16;
#pragma unroll
                for (int mt = 0; mt < 2; mt++) ldsm4(a[nxt][mt], sAs + aoffm[mt] + ko * 2);
#pragma unroll
                for (int p = 0; p < 4; p++) {
                    uint32_t r[4];
                    ldsm4t(r, sBs + boffn[p] + ko * 136 * 2);
                    b[nxt][p * 2][0] = r[0]; b[nxt][p * 2][1] = r[1];
                    b[nxt][p * 2 + 1][0] = r[2]; b[nxt][p * 2 + 1][1] = r[3];
                }
            }
#pragma unroll
            for (int mt = 0; mt < 2; mt++)
#pragma unroll
                for (int nt = 0; nt < 8; nt++) mma16(acc[mt][nt], a[cur][mt], b[cur][nt]);
        }
        slot = (slot + 1 == 3) ? 0 : slot + 1;
    }

#pragma unroll
    for (int mt = 0; mt < 2; mt++) {
        int r0 = row0 + mb + mt * 16 + gid;
        int bb = r0 >> 10, s0 = r0 & 1023;
#pragma unroll
        for (int nt = 0; nt < 8; nt++) {
            int col = col0 + nb + nt * 8 + 2 * tig;
            int hh = col >> 6, kk = col & 63;
            __half* base = O + (size_t)(hh * NB + bb) * SQ * DK;
            *(__half2*)(base + (size_t)s0 * DK + kk) =
                __floats2half2_rn(acc[mt][nt][0], acc[mt][nt][1]);
            *(__half2*)(base + (size_t)(s0 + 8) * DK + kk) =
                __floats2half2_rn(acc[mt][nt][2], acc[mt][nt][3]);
        }
    }
}

// ---------------------------------------------------------------------------
// Kernel 2: fused attention, register-resident P. 128-key OUTER tiles
// (8 barriers instead of 16), two 64-key compute halves per tile.
// ---------------------------------------------------------------------------
__global__ __launch_bounds__(256, 2) void attn_mma(
    const int* __restrict__ mask, float* __restrict__ sc)
{
    extern __shared__ __align__(16) __half smh[];
    __half* Qs  = smh;                    // [128][72]
    __half* Ksm = Qs + 128 * 72;          // [2][128][72]
    __half* Vsm = Ksm + 2 * 128 * 72;     // [2][128][72]

    const uint32_t qsm = (uint32_t)__cvta_generic_to_shared(Qs);
    const uint32_t ksm = (uint32_t)__cvta_generic_to_shared(Ksm);
    const uint32_t vsm = (uint32_t)__cvta_generic_to_shared(Vsm);
    const uint32_t TSZ = 128 * 72 * 2;
    const uint32_t HSZ = 64 * 72 * 2;     // half-tile offset

    const int hb = blockIdx.y;
    const int h  = hb >> 2, b = hb & 3;
    const int q0 = blockIdx.x * 128;
    const int t = threadIdx.x, warp = t >> 5, lane = t & 31;
    const int gid = lane >> 2, tig = lane & 3;
    const int lr = lane & 15;
    const int lc = (lane >> 4) * 8;

    const __half* qbase = g_qh + ((size_t)hb * SQ + q0) * DK;
    const __half* kbase = g_kh + (size_t)hb * SQ * DK;
    const __half* vbase = g_vh + (size_t)hb * SQ * DK;

    const uint32_t qoff = ((warp * 16 + lr) * 72 + lc) * 2;
    uint32_t koff[4], voff[4];
#pragma unroll
    for (int p = 0; p < 4; p++) {
        koff[p] = ((p * 16 + ((lane >> 4) & 1) * 8 + (lane & 7)) * 72
                   + ((lane >> 3) & 1) * 8) * 2;
        voff[p] = (lr * 72 + p * 16 + lc) * 2;
    }

    // prologue: Q (4 cp/thread) + K0/V0 128 rows (4+4 cp/thread)
#pragma unroll
    for (int u = 0; u < 4; u++) {
        int c = t + u * 256;
        int row = c >> 3, seg = c & 7;
        cp16(qsm + (row * 72 + seg * 8) * 2, qbase + (size_t)row * DK + seg * 8);
        cp16(ksm + (row * 72 + seg * 8) * 2, kbase + (size_t)row * DK + seg * 8);
        cp16(vsm + (row * 72 + seg * 8) * 2, vbase + (size_t)row * DK + seg * 8);
    }
    cp_commit();
    cp_wait0();
    __syncthreads();

    uint32_t qf[4][4];
#pragma unroll
    for (int j = 0; j < 4; j++) ldsm4(qf[j], qsm + qoff + j * 16 * 2);

    float Oacc[8][4] = {};
    float rs0 = 0.f, rs1 = 0.f;
    const float NEGINF = __int_as_float(0xff800000u);

    const int rl0 = warp * 16 + gid;
    const int rl1 = rl0 + 8;
    const int* mrow0 = mask + ((size_t)b * SQ + q0 + rl0) * SQ;
    const int* mrow1 = mask + ((size_t)b * SQ + q0 + rl1) * SQ;
    float* srow0 = sc + ((size_t)hb * SQ + q0 + rl0) * SQ;
    float* srow1 = sc + ((size_t)hb * SQ + q0 + rl1) * SQ;

    for (int kb = 0; kb < 8; kb++) {
        const int slot = kb & 1;
        if (kb > 0) { cp_wait0(); __syncthreads(); }
        if (kb + 1 < 8) {
            const int so = slot ^ 1;
            const __half* kp = kbase + (size_t)(kb + 1) * 128 * DK;
            const __half* vp = vbase + (size_t)(kb + 1) * 128 * DK;
#pragma unroll
            for (int u = 0; u < 4; u++) {
                int c = t + u * 256;
                int row = c >> 3, seg = c & 7;
                cp16(ksm + so * TSZ + (row * 72 + seg * 8) * 2, kp + (size_t)row * DK + seg * 8);
                cp16(vsm + so * TSZ + (row * 72 + seg * 8) * 2, vp + (size_t)row * DK + seg * 8);
            }
        }
        cp_commit();

        const uint32_t Kp = ksm + slot * TSZ;
        const uint32_t Vp = vsm + slot * TSZ;

#pragma unroll
        for (int hf = 0; hf < 2; hf++) {
            const uint32_t Kph = Kp + hf * HSZ;
            const uint32_t Vph = Vp + hf * HSZ;

            // S = Q @ K^T : depth-2 pipelined over j
            float Sacc[8][4] = {};
            {
                uint32_t bk[2][8][2];
#pragma unroll
                for (int p = 0; p < 4; p++) {
                    uint32_t r[4];
                    ldsm4(r, Kph + koff[p]);
                    bk[0][p * 2][0] = r[0]; bk[0][p * 2][1] = r[1];
                    bk[0][p * 2 + 1][0] = r[2]; bk[0][p * 2 + 1][1] = r[3];
                }
#pragma unroll
                for (int j = 0; j < 4; j++) {
                    const int cur = j & 1, nxt = cur ^ 1;
                    if (j < 3) {
#pragma unroll
                        for (int p = 0; p < 4; p++) {
                            uint32_t r[4];
                            ldsm4(r, Kph + koff[p] + (j + 1) * 16 * 2);
                            bk[nxt][p * 2][0] = r[0]; bk[nxt][p * 2][1] = r[1];
                            bk[nxt][p * 2 + 1][0] = r[2]; bk[nxt][p * 2 + 1][1] = r[3];
                        }
                    }
#pragma unroll
                    for (int nt = 0; nt < 8; nt++) mma16(Sacc[nt], qf[j], bk[cur][nt]);
                }
            }

            // scale, mask, streaming score stores, exp -> register A-fragments
            uint32_t apv[4][4];
            const int cb = kb * 128 + hf * 64;
#pragma unroll
            for (int nt = 0; nt < 8; nt++) {
                int cl = cb + nt * 8 + 2 * tig;
                int2 m0 = *(const int2*)(mrow0 + cl);
                int2 m1 = *(const int2*)(mrow1 + cl);
                float s00 = m0.x ? Sacc[nt][0] * 0.125f : NEGINF;
                float s01 = m0.y ? Sacc[nt][1] * 0.125f : NEGINF;
                float s10 = m1.x ? Sacc[nt][2] * 0.125f : NEGINF;
                float s11 = m1.y ? Sacc[nt][3] * 0.125f : NEGINF;
                __stcs((float2*)(srow0 + cl), make_float2(s00, s01));
                __stcs((float2*)(srow1 + cl), make_float2(s10, s11));
                float e00 = __expf(s00), e01 = __expf(s01);
                float e10 = __expf(s10), e11 = __expf(s11);
                rs0 += e00 + e01;
                rs1 += e10 + e11;
                int j = nt >> 1;
                if ((nt & 1) == 0) {
                    apv[j][0] = h2u(__floats2half2_rn(e00, e01));
                    apv[j][1] = h2u(__floats2half2_rn(e10, e11));
                } else {
                    apv[j][2] = h2u(__floats2half2_rn(e00, e01));
                    apv[j][3] = h2u(__floats2half2_rn(e10, e11));
                }
            }

            // O += P @ V : depth-2 pipelined over j
            {
                uint32_t bv[2][8][2];
#pragma unroll
                for (int p = 0; p < 4; p++) {
                    uint32_t r[4];
                    ldsm4t(r, Vph + voff[p]);
                    bv[0][p * 2][0] = r[0]; bv[0][p * 2][1] = r[1];
                    bv[0][p * 2 + 1][0] = r[2]; bv[0][p * 2 + 1][1] = r[3];
                }
#pragma unroll
                for (int j = 0; j < 4; j++) {
                    const int cur = j & 1, nxt = cur ^ 1;
                    if (j < 3) {
#pragma unroll
                        for (int p = 0; p < 4; p++) {
                            uint32_t r[4];
                            ldsm4t(r, Vph + voff[p] + (j + 1) * 16 * 72 * 2);
                            bv[nxt][p * 2][0] = r[0]; bv[nxt][p * 2][1] = r[1];
                            bv[nxt][p * 2 + 1][0] = r[2]; bv[nxt][p * 2 + 1][1] = r[3];
                        }
                    }
#pragma unroll
                    for (int nt = 0; nt < 8; nt++) mma16(Oacc[nt], apv[j], bv[cur][nt]);
                }
            }
        }
    }

    rs0 += __shfl_xor_sync(0xffffffffu, rs0, 1);
    rs0 += __shfl_xor_sync(0xffffffffu, rs0, 2);
    rs1 += __shfl_xor_sync(0xffffffffu, rs1, 1);
    rs1 += __shfl_xor_sync(0xffffffffu, rs1, 2);
    float inv0 = 1.0f / rs0, inv1 = 1.0f / rs1;

    __half* c0 = g_ch + ((size_t)b * SQ + q0 + rl0) * DM + h * DK;
    __half* c1 = g_ch + ((size_t)b * SQ + q0 + rl1) * DM + h * DK;
#pragma unroll
    for (int nt = 0; nt < 8; nt++) {
        int cl = nt * 8 + 2 * tig;
        *(__half2*)(c0 + cl) = __floats2half2_rn(Oacc[nt][0] * inv0, Oacc[nt][1] * inv0);
        *(__half2*)(c1 + cl) = __floats2half2_rn(Oacc[nt][2] * inv1, Oacc[nt][3] * inv1);
    }
}

// ---------------------------------------------------------------------------
// Kernel 3: out = concat @ Wo, BK=64, 3-stage, frag-first ordering. fp32 out.
// ---------------------------------------------------------------------------
__global__ __launch_bounds__(256, 2) void outproj_mma(float* __restrict__ out)
{
    const int row0 = blockIdx.x * 128;
    const int col0 = blockIdx.y * 128;

    extern __shared__ __align__(16) __half sh[];
    __half* As = sh;
    __half* Bs = sh + 3 * 128 * 72;
    const uint32_t sA = (uint32_t)__cvta_generic_to_shared(As);
    const uint32_t sB = (uint32_t)__cvta_generic_to_shared(Bs);
    const uint32_t ASZ = 128 * 72 * 2, BSZ = 64 * 136 * 2;

    const int t    = threadIdx.x;
    const int warp = t >> 5, lane = t & 31;
    const int gid  = lane >> 2, tig = lane & 3;
    const int mb   = (warp >> 1) * 32;
    const int nb   = (warp & 1) * 64;
    const int lr   = lane & 15;
    const int lc   = (lane >> 4) * 8;

    uint32_t aoffm[2], boffn[4];
#pragma unroll
    for (int mt = 0; mt < 2; mt++) aoffm[mt] = ((mb + mt * 16 + lr) * 72 + lc) * 2;
#pragma unroll
    for (int p = 0; p < 4; p++) boffn[p] = (lr * 136 + nb + p * 16 + lc) * 2;

    const __half* aptr[4]; uint32_t aoff[4];
    const __half* bptr[4]; uint32_t boff[4];
#pragma unroll
    for (int u = 0; u < 4; u++) {
        int c = t + u * 256;
        int arow = c >> 3, aseg = c & 7;
        aptr[u] = g_ch + (size_t)(row0 + arow) * DM + aseg * 8;
        aoff[u] = (arow * 72 + aseg * 8) * 2;
        int brow = c >> 4, bseg = c & 15;
        bptr[u] = g_wo + (size_t)brow * DM + col0 + bseg * 8;
        boff[u] = (brow * 136 + bseg * 8) * 2;
    }

    float acc[2][8][4] = {};
    const int NT = 16;

#pragma unroll
    for (int p = 0; p < 2; p++) {
#pragma unroll
        for (int u = 0; u < 4; u++) {
            cp16(sA + p * ASZ + aoff[u], aptr[u] + p * 64);
            cp16(sB + p * BSZ + boff[u], bptr[u] + (size_t)(p * 64) * DM);
        }
        cp_commit();
    }

    int slot = 0;
    for (int tt = 0; tt < NT; tt++) {
        cp_wait1();
        __syncthreads();

        const uint32_t sAs = sA + slot * ASZ;
        const uint32_t sBs = sB + slot * BSZ;

        uint32_t a[2][2][4], b[2][8][2];
#pragma unroll
        for (int mt = 0; mt < 2; mt++) ldsm4(a[0][mt], sAs + aoffm[mt]);
#pragma unroll
        for (int p = 0; p < 4; p++) {
            uint32_t r[4];
            ldsm4t(r, sBs + boffn[p]);
            b[0][p * 2][0] = r[0]; b[0][p * 2][1] = r[1];
            b[0][p * 2 + 1][0] = r[2]; b[0][p * 2 + 1][1] = r[3];
        }

        if (tt + 2 < NT) {
            const int ps = (tt + 2) % 3;
            const int kt = (tt + 2) * 64;
#pragma unroll
            for (int u = 0; u < 4; u++) {
                cp16(sA + ps * ASZ + aoff[u], aptr[u] + kt);
                cp16(sB + ps * BSZ + boff[u], bptr[u] + (size_t)kt * DM);
            }
        }
        cp_commit();

#pragma unroll
        for (int ks = 0; ks < 4; ks++) {
            const int cur = ks & 1, nxt = cur ^ 1;
            if (ks < 3) {
                const int ko = (ks + 1) * 16;
#pragma unroll
                for (int mt = 0; mt < 2; mt++) ldsm4(a[nxt][mt], sAs + aoffm[mt] + ko * 2);
#pragma unroll
                for (int p = 0; p < 4; p++) {
                    uint32_t r[4];
                    ldsm4t(r, sBs + boffn[p] + ko * 136 * 2);
                    b[nxt][p * 2][0] = r[0]; b[nxt][p * 2][1] = r[1];
                    b[nxt][p * 2 + 1][0] = r[2]; b[nxt][p * 2 + 1][1] = r[3];
                }
            }
#pragma unroll
            for (int mt = 0; mt < 2; mt++)
#pragma unroll
                for (int nt = 0; nt < 8; nt++) mma16(acc[mt][nt], a[cur][mt], b[cur][nt]);
        }
        slot = (slot + 1 == 3) ? 0 : slot + 1;
    }

#pragma unroll
    for (int mt = 0; mt < 2; mt++) {
        int r = row0 + mb + mt * 16 + gid;
#pragma unroll
        for (int nt = 0; nt < 8; nt++) {
            int col = col0 + nb + nt * 8 + 2 * tig;
            *(float2*)(out + (size_t)r * DM + col)       = make_float2(acc[mt][nt][0], acc[mt][nt][1]);
            *(float2*)(out + (size_t)(r + 8) * DM + col) = make_float2(acc[mt][nt][2], acc[mt][nt][3]);
        }
    }
}

// ---------------------------------------------------------------------------
extern "C" void kernel_launch(void* const* d_in, const int* in_sizes, int n_in,
                              void* d_out, int out_size)
{
    const float* q    = (const float*)d_in[0];
    const float* k    = (const float*)d_in[1];
    const float* v    = (const float*)d_in[2];
    const int*   mask = (const int*)  d_in[3];
    const float* Wq   = (const float*)d_in[4];
    const float* Wk   = (const float*)d_in[5];
    const float* Wv   = (const float*)d_in[6];
    const float* Wo   = (const float*)d_in[7];

    float* out = (float*)d_out;
    float* scp = out + (size_t)MR * DM;

    static int smem_set = 0;
    if (!smem_set) {
        cudaFuncSetAttribute(proj_mma,    cudaFuncAttributeMaxDynamicSharedMemorySize, 107520);
        cudaFuncSetAttribute(outproj_mma, cudaFuncAttributeMaxDynamicSharedMemorySize, 107520);
        cudaFuncSetAttribute(attn_mma,    cudaFuncAttributeMaxDynamicSharedMemorySize, 92160);
        smem_set = 1;
    }

    prep_all   <<<8192, 256>>>(q, k, v, Wq, Wk, Wv, Wo);
    proj_mma   <<<dim3(32, 8, 3), 256, 107520>>>();
    attn_mma   <<<dim3(8, 64), 256, 92160>>>(mask, scp);
    outproj_mma<<<dim3(32, 8), 256, 107520>>>(out);
}

// round 12
// speedup vs baseline: 1.0002x; 1.0002x over previous
#include <cuda_runtime.h>
#include <cuda_fp16.h>
#include <cstdint>

#define NH 16
#define NB 4
#define SQ 1024
#define DM 1024
#define DK 64
#define MR (NB * SQ)
#define HB (NH * NB)

// fp16 scratch (__device__ globals per allocation-free rule)
__device__ __half g_xq[(size_t)MR * DM];
__device__ __half g_xk[(size_t)MR * DM];
__device__ __half g_xv[(size_t)MR * DM];
__device__ __half g_wq[(size_t)NH * DM * DK];
__device__ __half g_wk[(size_t)NH * DM * DK];
__device__ __half g_wv[(size_t)NH * DM * DK];
__device__ __half g_wo[(size_t)DM * DM];
__device__ __half g_qh[(size_t)HB * SQ * DK];
__device__ __half g_kh[(size_t)HB * SQ * DK];
__device__ __half g_vh[(size_t)HB * SQ * DK];
__device__ __half g_ch[(size_t)MR * DM];

__device__ __forceinline__ uint32_t h2u(__half2 h) { return *(uint32_t*)&h; }

__device__ __forceinline__ void ldsm4(uint32_t* r, uint32_t addr) {
    asm volatile("ldmatrix.sync.aligned.m8n8.x4.shared.b16 {%0,%1,%2,%3}, [%4];"
        : "=r"(r[0]), "=r"(r[1]), "=r"(r[2]), "=r"(r[3]) : "r"(addr));
}
__device__ __forceinline__ void ldsm4t(uint32_t* r, uint32_t addr) {
    asm volatile("ldmatrix.sync.aligned.m8n8.x4.trans.shared.b16 {%0,%1,%2,%3}, [%4];"
        : "=r"(r[0]), "=r"(r[1]), "=r"(r[2]), "=r"(r[3]) : "r"(addr));
}
__device__ __forceinline__ void mma16(float* d, const uint32_t* a, const uint32_t* b) {
    asm volatile("mma.sync.aligned.m16n8k16.row.col.f32.f16.f16.f32 "
        "{%0,%1,%2,%3}, {%4,%5,%6,%7}, {%8,%9}, {%0,%1,%2,%3};"
        : "+f"(d[0]), "+f"(d[1]), "+f"(d[2]), "+f"(d[3])
        : "r"(a[0]), "r"(a[1]), "r"(a[2]), "r"(a[3]), "r"(b[0]), "r"(b[1]));
}
__device__ __forceinline__ void cp16(uint32_t dst, const void* src) {
    asm volatile("cp.async.cg.shared.global [%0], [%1], 16;" :: "r"(dst), "l"(src));
}
__device__ __forceinline__ void cp_commit() { asm volatile("cp.async.commit_group;"); }
__device__ __forceinline__ void cp_wait0() { asm volatile("cp.async.wait_group 0;"); }
__device__ __forceinline__ void cp_wait1() { asm volatile("cp.async.wait_group 1;"); }

// ---------------------------------------------------------------------------
// Kernel 0: single fused fp32->fp16 conversion for all 7 input tensors.
// ---------------------------------------------------------------------------
__global__ __launch_bounds__(256) void prep_all(
    const float* __restrict__ q, const float* __restrict__ k, const float* __restrict__ v,
    const float* __restrict__ wq, const float* __restrict__ wk, const float* __restrict__ wv,
    const float* __restrict__ wo)
{
    const int bb = blockIdx.x;
    const float* src; __half* dst; int inner;
    if (bb < 6144) {
        int which = bb >> 11;
        src = (which == 0) ? q : (which == 1) ? k : v;
        dst = (which == 0) ? g_xq : (which == 1) ? g_xk : g_xv;
        inner = bb & 2047;
    } else {
        int which = (bb - 6144) >> 9;
        src = (which == 0) ? wq : (which == 1) ? wk : (which == 2) ? wv : wo;
        dst = (which == 0) ? g_wq : (which == 1) ? g_wk : (which == 2) ? g_wv : g_wo;
        inner = (bb - 6144) & 511;
    }
    size_t i = (size_t)inner * 256 + threadIdx.x;
    float4 a = ((const float4*)src)[i * 2];
    float4 b = ((const float4*)src)[i * 2 + 1];
    uint4 o;
    o.x = h2u(__floats2half2_rn(a.x, a.y));
    o.y = h2u(__floats2half2_rn(a.z, a.w));
    o.z = h2u(__floats2half2_rn(b.x, b.y));
    o.w = h2u(__floats2half2_rn(b.z, b.w));
    ((uint4*)dst)[i] = o;
}

// ---------------------------------------------------------------------------
// Kernel 1: per-head projections. 512 threads (16 warps, 4x4), warp tile
// 32x32, BK=64, 3-stage cp.async ring, depth-1 frags, 64-reg cap -> 32 warps/SM.
// ---------------------------------------------------------------------------
__global__ __launch_bounds__(512, 2) void proj_mma()
{
    const int which = blockIdx.z;
    const __half* X = (which == 0) ? g_xq : (which == 1) ? g_xk : g_xv;
    const __half* W = (which == 0) ? g_wq : (which == 1) ? g_wk : g_wv;
    __half* O       = (which == 0) ? g_qh : (which == 1) ? g_kh : g_vh;
    const int row0 = blockIdx.x * 128;
    const int col0 = blockIdx.y * 128;

    extern __shared__ __align__(16) __half sh[];
    __half* As = sh;                  // [3][128*72]
    __half* Bs = sh + 3 * 128 * 72;   // [3][64*136]
    const uint32_t sA = (uint32_t)__cvta_generic_to_shared(As);
    const uint32_t sB = (uint32_t)__cvta_generic_to_shared(Bs);
    const uint32_t ASZ = 128 * 72 * 2, BSZ = 64 * 136 * 2;

    const int t    = threadIdx.x;
    const int warp = t >> 5, lane = t & 31;
    const int gid  = lane >> 2, tig = lane & 3;
    const int wm   = warp >> 2;        // 0..3 -> m strip of 32
    const int wn   = warp & 3;         // 0..3 -> n strip of 32
    const int lr   = lane & 15;
    const int lc   = (lane >> 4) * 8;

    uint32_t aoffm[2], boffn[2];
#pragma unroll
    for (int mt = 0; mt < 2; mt++) aoffm[mt] = ((wm * 32 + mt * 16 + lr) * 72 + lc) * 2;
#pragma unroll
    for (int p = 0; p < 2; p++) boffn[p] = (lr * 136 + wn * 32 + p * 16 + lc) * 2;

    // cp.async: A 2/thread (128 rows x 8 segs), B 2/thread (64 rows x 16 segs)
    const __half* aptr[2]; uint32_t aoff[2];
    const __half* bptr[2]; uint32_t boff[2];
#pragma unroll
    for (int u = 0; u < 2; u++) {
        int c = t + u * 512;
        int arow = c >> 3, aseg = c & 7;
        aptr[u] = X + (size_t)(row0 + arow) * DM + aseg * 8;
        aoff[u] = (arow * 72 + aseg * 8) * 2;
        int brow = c >> 4, bseg = c & 15;
        int colh = col0 + bseg * 8, hh = colh >> 6, kk = colh & 63;
        bptr[u] = W + (size_t)hh * DM * DK + (size_t)brow * DK + kk;
        boff[u] = (brow * 136 + bseg * 8) * 2;
    }

    float acc[2][4][4] = {};
    const int NT = 16;   // 1024 / 64

#pragma unroll
    for (int p = 0; p < 2; p++) {
#pragma unroll
        for (int u = 0; u < 2; u++) {
            cp16(sA + p * ASZ + aoff[u], aptr[u] + p * 64);
            cp16(sB + p * BSZ + boff[u], bptr[u] + (size_t)(p * 64) * DK);
        }
        cp_commit();
    }

    int slot = 0;
    for (int tt = 0; tt < NT; tt++) {
        cp_wait1();
        __syncthreads();

        if (tt + 2 < NT) {
            const int ps = (tt + 2) % 3;
            const int kt = (tt + 2) * 64;
#pragma unroll
            for (int u = 0; u < 2; u++) {
                cp16(sA + ps * ASZ + aoff[u], aptr[u] + kt);
                cp16(sB + ps * BSZ + boff[u], bptr[u] + (size_t)kt * DK);
            }
        }
        cp_commit();

        const uint32_t sAs = sA + slot * ASZ;
        const uint32_t sBs = sB + slot * BSZ;
#pragma unroll
        for (int ks = 0; ks < 4; ks++) {
            const int ko = ks * 16;
            uint32_t a[2][4], b[4][2];
#pragma unroll
            for (int mt = 0; mt < 2; mt++) ldsm4(a[mt], sAs + aoffm[mt] + ko * 2);
#pragma unroll
            for (int p = 0; p < 2; p++) {
                uint32_t r[4];
                ldsm4t(r, sBs + boffn[p] + ko * 136 * 2);
                b[p * 2][0] = r[0]; b[p * 2][1] = r[1];
                b[p * 2 + 1][0] = r[2]; b[p * 2 + 1][1] = r[3];
            }
#pragma unroll
            for (int mt = 0; mt < 2; mt++)
#pragma unroll
                for (int nt = 0; nt < 4; nt++) mma16(acc[mt][nt], a[mt], b[nt]);
        }
        slot = (slot + 1 == 3) ? 0 : slot + 1;
    }

#pragma unroll
    for (int mt = 0; mt < 2; mt++) {
        int r0 = row0 + wm * 32 + mt * 16 + gid;
        int bb = r0 >> 10, s0 = r0 & 1023;
#pragma unroll
        for (int nt = 0; nt < 4; nt++) {
            int col = col0 + wn * 32 + nt * 8 + 2 * tig;
            int hh = col >> 6, kk = col & 63;
            __half* base = O + (size_t)(hh * NB + bb) * SQ * DK;
            *(__half2*)(base + (size_t)s0 * DK + kk) =
                __floats2half2_rn(acc[mt][nt][0], acc[mt][nt][1]);
            *(__half2*)(base + (size_t)(s0 + 8) * DK + kk) =
                __floats2half2_rn(acc[mt][nt][2], acc[mt][nt][3]);
        }
    }
}

// ---------------------------------------------------------------------------
// Kernel 2: fused attention, register-resident P, 128-key outer tiles.
// (unchanged from R10/R11 — passing at this perf)
// ---------------------------------------------------------------------------
__global__ __launch_bounds__(256, 2) void attn_mma(
    const int* __restrict__ mask, float* __restrict__ sc)
{
    extern __shared__ __align__(16) __half smh[];
    __half* Qs  = smh;                    // [128][72]
    __half* Ksm = Qs + 128 * 72;          // [2][128][72]
    __half* Vsm = Ksm + 2 * 128 * 72;     // [2][128][72]

    const uint32_t qsm = (uint32_t)__cvta_generic_to_shared(Qs);
    const uint32_t ksm = (uint32_t)__cvta_generic_to_shared(Ksm);
    const uint32_t vsm = (uint32_t)__cvta_generic_to_shared(Vsm);
    const uint32_t TSZ = 128 * 72 * 2;
    const uint32_t HSZ = 64 * 72 * 2;

    const int hb = blockIdx.y;
    const int h  = hb >> 2, b = hb & 3;
    const int q0 = blockIdx.x * 128;
    const int t = threadIdx.x, warp = t >> 5, lane = t & 31;
    const int gid = lane >> 2, tig = lane & 3;
    const int lr = lane & 15;
    const int lc = (lane >> 4) * 8;

    const __half* qbase = g_qh + ((size_t)hb * SQ + q0) * DK;
    const __half* kbase = g_kh + (size_t)hb * SQ * DK;
    const __half* vbase = g_vh + (size_t)hb * SQ * DK;

    const uint32_t qoff = ((warp * 16 + lr) * 72 + lc) * 2;
    uint32_t koff[4], voff[4];
#pragma unroll
    for (int p = 0; p < 4; p++) {
        koff[p] = ((p * 16 + ((lane >> 4) & 1) * 8 + (lane & 7)) * 72
                   + ((lane >> 3) & 1) * 8) * 2;
        voff[p] = (lr * 72 + p * 16 + lc) * 2;
    }

#pragma unroll
    for (int u = 0; u < 4; u++) {
        int c = t + u * 256;
        int row = c >> 3, seg = c & 7;
        cp16(qsm + (row * 72 + seg * 8) * 2, qbase + (size_t)row * DK + seg * 8);
        cp16(ksm + (row * 72 + seg * 8) * 2, kbase + (size_t)row * DK + seg * 8);
        cp16(vsm + (row * 72 + seg * 8) * 2, vbase + (size_t)row * DK + seg * 8);
    }
    cp_commit();
    cp_wait0();
    __syncthreads();

    uint32_t qf[4][4];
#pragma unroll
    for (int j = 0; j < 4; j++) ldsm4(qf[j], qsm + qoff + j * 16 * 2);

    float Oacc[8][4] = {};
    float rs0 = 0.f, rs1 = 0.f;
    const float NEGINF = __int_as_float(0xff800000u);

    const int rl0 = warp * 16 + gid;
    const int rl1 = rl0 + 8;
    const int* mrow0 = mask + ((size_t)b * SQ + q0 + rl0) * SQ;
    const int* mrow1 = mask + ((size_t)b * SQ + q0 + rl1) * SQ;
    float* srow0 = sc + ((size_t)hb * SQ + q0 + rl0) * SQ;
    float* srow1 = sc + ((size_t)hb * SQ + q0 + rl1) * SQ;

    for (int kb = 0; kb < 8; kb++) {
        const int slot = kb & 1;
        if (kb > 0) { cp_wait0(); __syncthreads(); }
        if (kb + 1 < 8) {
            const int so = slot ^ 1;
            const __half* kp = kbase + (size_t)(kb + 1) * 128 * DK;
            const __half* vp = vbase + (size_t)(kb + 1) * 128 * DK;
#pragma unroll
            for (int u = 0; u < 4; u++) {
                int c = t + u * 256;
                int row = c >> 3, seg = c & 7;
                cp16(ksm + so * TSZ + (row * 72 + seg * 8) * 2, kp + (size_t)row * DK + seg * 8);
                cp16(vsm + so * TSZ + (row * 72 + seg * 8) * 2, vp + (size_t)row * DK + seg * 8);
            }
        }
        cp_commit();

        const uint32_t Kp = ksm + slot * TSZ;
        const uint32_t Vp = vsm + slot * TSZ;

#pragma unroll
        for (int hf = 0; hf < 2; hf++) {
            const uint32_t Kph = Kp + hf * HSZ;
            const uint32_t Vph = Vp + hf * HSZ;

            float Sacc[8][4] = {};
            {
                uint32_t bk[2][8][2];
#pragma unroll
                for (int p = 0; p < 4; p++) {
                    uint32_t r[4];
                    ldsm4(r, Kph + koff[p]);
                    bk[0][p * 2][0] = r[0]; bk[0][p * 2][1] = r[1];
                    bk[0][p * 2 + 1][0] = r[2]; bk[0][p * 2 + 1][1] = r[3];
                }
#pragma unroll
                for (int j = 0; j < 4; j++) {
                    const int cur = j & 1, nxt = cur ^ 1;
                    if (j < 3) {
#pragma unroll
                        for (int p = 0; p < 4; p++) {
                            uint32_t r[4];
                            ldsm4(r, Kph + koff[p] + (j + 1) * 16 * 2);
                            bk[nxt][p * 2][0] = r[0]; bk[nxt][p * 2][1] = r[1];
                            bk[nxt][p * 2 + 1][0] = r[2]; bk[nxt][p * 2 + 1][1] = r[3];
                        }
                    }
#pragma unroll
                    for (int nt = 0; nt < 8; nt++) mma16(Sacc[nt], qf[j], bk[cur][nt]);
                }
            }

            uint32_t apv[4][4];
            const int cb = kb * 128 + hf * 64;
#pragma unroll
            for (int nt = 0; nt < 8; nt++) {
                int cl = cb + nt * 8 + 2 * tig;
                int2 m0 = *(const int2*)(mrow0 + cl);
                int2 m1 = *(const int2*)(mrow1 + cl);
                float s00 = m0.x ? Sacc[nt][0] * 0.125f : NEGINF;
                float s01 = m0.y ? Sacc[nt][1] * 0.125f : NEGINF;
                float s10 = m1.x ? Sacc[nt][2] * 0.125f : NEGINF;
                float s11 = m1.y ? Sacc[nt][3] * 0.125f : NEGINF;
                __stcs((float2*)(srow0 + cl), make_float2(s00, s01));
                __stcs((float2*)(srow1 + cl), make_float2(s10, s11));
                float e00 = __expf(s00), e01 = __expf(s01);
                float e10 = __expf(s10), e11 = __expf(s11);
                rs0 += e00 + e01;
                rs1 += e10 + e11;
                int j = nt >> 1;
                if ((nt & 1) == 0) {
                    apv[j][0] = h2u(__floats2half2_rn(e00, e01));
                    apv[j][1] = h2u(__floats2half2_rn(e10, e11));
                } else {
                    apv[j][2] = h2u(__floats2half2_rn(e00, e01));
                    apv[j][3] = h2u(__floats2half2_rn(e10, e11));
                }
            }

            {
                uint32_t bv[2][8][2];
#pragma unroll
                for (int p = 0; p < 4; p++) {
                    uint32_t r[4];
                    ldsm4t(r, Vph + voff[p]);
                    bv[0][p * 2][0] = r[0]; bv[0][p * 2][1] = r[1];
                    bv[0][p * 2 + 1][0] = r[2]; bv[0][p * 2 + 1][1] = r[3];
                }
#pragma unroll
                for (int j = 0; j < 4; j++) {
                    const int cur = j & 1, nxt = cur ^ 1;
                    if (j < 3) {
#pragma unroll
                        for (int p = 0; p < 4; p++) {
                            uint32_t r[4];
                            ldsm4t(r, Vph + voff[p] + (j + 1) * 16 * 72 * 2);
                            bv[nxt][p * 2][0] = r[0]; bv[nxt][p * 2][1] = r[1];
                            bv[nxt][p * 2 + 1][0] = r[2]; bv[nxt][p * 2 + 1][1] = r[3];
                        }
                    }
#pragma unroll
                    for (int nt = 0; nt < 8; nt++) mma16(Oacc[nt], apv[j], bv[cur][nt]);
                }
            }
        }
    }

    rs0 += __shfl_xor_sync(0xffffffffu, rs0, 1);
    rs0 += __shfl_xor_sync(0xffffffffu, rs0, 2);
    rs1 += __shfl_xor_sync(0xffffffffu, rs1, 1);
    rs1 += __shfl_xor_sync(0xffffffffu, rs1, 2);
    float inv0 = 1.0f / rs0, inv1 = 1.0f / rs1;

    __half* c0 = g_ch + ((size_t)b * SQ + q0 + rl0) * DM + h * DK;
    __half* c1 = g_ch + ((size_t)b * SQ + q0 + rl1) * DM + h * DK;
#pragma unroll
    for (int nt = 0; nt < 8; nt++) {
        int cl = nt * 8 + 2 * tig;
        *(__half2*)(c0 + cl) = __floats2half2_rn(Oacc[nt][0] * inv0, Oacc[nt][1] * inv0);
        *(__half2*)(c1 + cl) = __floats2half2_rn(Oacc[nt][2] * inv1, Oacc[nt][3] * inv1);
    }
}

// ---------------------------------------------------------------------------
// Kernel 3: out = concat @ Wo. 512 threads, 4x4 warps, BK=64, 3-stage. fp32 out.
// ---------------------------------------------------------------------------
__global__ __launch_bounds__(512, 2) void outproj_mma(float* __restrict__ out)
{
    const int row0 = blockIdx.x * 128;
    const int col0 = blockIdx.y * 128;

    extern __shared__ __align__(16) __half sh[];
    __half* As = sh;
    __half* Bs = sh + 3 * 128 * 72;
    const uint32_t sA = (uint32_t)__cvta_generic_to_shared(As);
    const uint32_t sB = (uint32_t)__cvta_generic_to_shared(Bs);
    const uint32_t ASZ = 128 * 72 * 2, BSZ = 64 * 136 * 2;

    const int t    = threadIdx.x;
    const int warp = t >> 5, lane = t & 31;
    const int gid  = lane >> 2, tig = lane & 3;
    const int wm   = warp >> 2;
    const int wn   = warp & 3;
    const int lr   = lane & 15;
    const int lc   = (lane >> 4) * 8;

    uint32_t aoffm[2], boffn[2];
#pragma unroll
    for (int mt = 0; mt < 2; mt++) aoffm[mt] = ((wm * 32 + mt * 16 + lr) * 72 + lc) * 2;
#pragma unroll
    for (int p = 0; p < 2; p++) boffn[p] = (lr * 136 + wn * 32 + p * 16 + lc) * 2;

    const __half* aptr[2]; uint32_t aoff[2];
    const __half* bptr[2]; uint32_t boff[2];
#pragma unroll
    for (int u = 0; u < 2; u++) {
        int c = t + u * 512;
        int arow = c >> 3, aseg = c & 7;
        aptr[u] = g_ch + (size_t)(row0 + arow) * DM + aseg * 8;
        aoff[u] = (arow * 72 + aseg * 8) * 2;
        int brow = c >> 4, bseg = c & 15;
        bptr[u] = g_wo + (size_t)brow * DM + col0 + bseg * 8;
        boff[u] = (brow * 136 + bseg * 8) * 2;
    }

    float acc[2][4][4] = {};
    const int NT = 16;

#pragma unroll
    for (int p = 0; p < 2; p++) {
#pragma unroll
        for (int u = 0; u < 2; u++) {
            cp16(sA + p * ASZ + aoff[u], aptr[u] + p * 64);
            cp16(sB + p * BSZ + boff[u], bptr[u] + (size_t)(p * 64) * DM);
        }
        cp_commit();
    }

    int slot = 0;
    for (int tt = 0; tt < NT; tt++) {
        cp_wait1();
        __syncthreads();

        if (tt + 2 < NT) {
            const int ps = (tt + 2) % 3;
            const int kt = (tt + 2) * 64;
#pragma unroll
            for (int u = 0; u < 2; u++) {
                cp16(sA + ps * ASZ + aoff[u], aptr[u] + kt);
                cp16(sB + ps * BSZ + boff[u], bptr[u] + (size_t)kt * DM);
            }
        }
        cp_commit();

        const uint32_t sAs = sA + slot * ASZ;
        const uint32_t sBs = sB + slot * BSZ;
#pragma unroll
        for (int ks = 0; ks < 4; ks++) {
            const int ko = ks * 16;
            uint32_t a[2][4], b[4][2];
#pragma unroll
            for (int mt = 0; mt < 2; mt++) ldsm4(a[mt], sAs + aoffm[mt] + ko * 2);
#pragma unroll
            for (int p = 0; p < 2; p++) {
                uint32_t r[4];
                ldsm4t(r, sBs + boffn[p] + ko * 136 * 2);
                b[p * 2][0] = r[0]; b[p * 2][1] = r[1];
                b[p * 2 + 1][0] = r[2]; b[p * 2 + 1][1] = r[3];
            }
#pragma unroll
            for (int mt = 0; mt < 2; mt++)
#pragma unroll
                for (int nt = 0; nt < 4; nt++) mma16(acc[mt][nt], a[mt], b[nt]);
        }
        slot = (slot + 1 == 3) ? 0 : slot + 1;
    }

#pragma unroll
    for (int mt = 0; mt < 2; mt++) {
        int r = row0 + wm * 32 + mt * 16 + gid;
#pragma unroll
        for (int nt = 0; nt < 4; nt++) {
            int col = col0 + wn * 32 + nt * 8 + 2 * tig;
            *(float2*)(out + (size_t)r * DM + col)       = make_float2(acc[mt][nt][0], acc[mt][nt][1]);
            *(float2*)(out + (size_t)(r + 8) * DM + col) = make_float2(acc[mt][nt][2], acc[mt][nt][3]);
        }
    }
}

// ---------------------------------------------------------------------------
extern "C" void kernel_launch(void* const* d_in, const int* in_sizes, int n_in,
                              void* d_out, int out_size)
{
    const float* q    = (const float*)d_in[0];
    const float* k    = (const float*)d_in[1];
    const float* v    = (const float*)d_in[2];
    const int*   mask = (const int*)  d_in[3];
    const float* Wq   = (const float*)d_in[4];
    const float* Wk   = (const float*)d_in[5];
    const float* Wv   = (const float*)d_in[6];
    const float* Wo   = (const float*)d_in[7];

    float* out = (float*)d_out;
    float* scp = out + (size_t)MR * DM;

    static int smem_set = 0;
    if (!smem_set) {
        cudaFuncSetAttribute(proj_mma,    cudaFuncAttributeMaxDynamicSharedMemorySize, 107520);
        cudaFuncSetAttribute(outproj_mma, cudaFuncAttributeMaxDynamicSharedMemorySize, 107520);
        cudaFuncSetAttribute(attn_mma,    cudaFuncAttributeMaxDynamicSharedMemorySize, 92160);
        smem_set = 1;
    }

    prep_all   <<<8192, 256>>>(q, k, v, Wq, Wk, Wv, Wo);
    proj_mma   <<<dim3(32, 8, 3), 512, 107520>>>();
    attn_mma   <<<dim3(8, 64), 256, 92160>>>(mask, scp);
    outproj_mma<<<dim3(32, 8), 512, 107520>>>(out);
}

// round 13
// speedup vs baseline: 1.1663x; 1.1660x over previous
#include <cuda_runtime.h>
#include <cuda_fp16.h>
#include <cstdint>

#define NH 16
#define NB 4
#define SQ 1024
#define DM 1024
#define DK 64
#define MR (NB * SQ)
#define HB (NH * NB)

// fp16 scratch (__device__ globals per allocation-free rule)
__device__ __half g_xq[(size_t)MR * DM];
__device__ __half g_xk[(size_t)MR * DM];
__device__ __half g_xv[(size_t)MR * DM];
__device__ __half g_wq[(size_t)NH * DM * DK];
__device__ __half g_wk[(size_t)NH * DM * DK];
__device__ __half g_wv[(size_t)NH * DM * DK];
__device__ __half g_wo[(size_t)DM * DM];
__device__ __half g_qh[(size_t)HB * SQ * DK];
__device__ __half g_kh[(size_t)HB * SQ * DK];
__device__ __half g_vh[(size_t)HB * SQ * DK];
__device__ __half g_ch[(size_t)MR * DM];
__device__ uint32_t g_mbits[(size_t)NB * SQ * (SQ / 32)];   // 1 bit per mask elem

__device__ __forceinline__ uint32_t h2u(__half2 h) { return *(uint32_t*)&h; }

__device__ __forceinline__ void ldsm4(uint32_t* r, uint32_t addr) {
    asm volatile("ldmatrix.sync.aligned.m8n8.x4.shared.b16 {%0,%1,%2,%3}, [%4];"
        : "=r"(r[0]), "=r"(r[1]), "=r"(r[2]), "=r"(r[3]) : "r"(addr));
}
__device__ __forceinline__ void ldsm4t(uint32_t* r, uint32_t addr) {
    asm volatile("ldmatrix.sync.aligned.m8n8.x4.trans.shared.b16 {%0,%1,%2,%3}, [%4];"
        : "=r"(r[0]), "=r"(r[1]), "=r"(r[2]), "=r"(r[3]) : "r"(addr));
}
__device__ __forceinline__ void mma16(float* d, const uint32_t* a, const uint32_t* b) {
    asm volatile("mma.sync.aligned.m16n8k16.row.col.f32.f16.f16.f32 "
        "{%0,%1,%2,%3}, {%4,%5,%6,%7}, {%8,%9}, {%0,%1,%2,%3};"
        : "+f"(d[0]), "+f"(d[1]), "+f"(d[2]), "+f"(d[3])
        : "r"(a[0]), "r"(a[1]), "r"(a[2]), "r"(a[3]), "r"(b[0]), "r"(b[1]));
}
__device__ __forceinline__ void cp16(uint32_t dst, const void* src) {
    asm volatile("cp.async.cg.shared.global [%0], [%1], 16;" :: "r"(dst), "l"(src));
}
__device__ __forceinline__ void cp_commit() { asm volatile("cp.async.commit_group;"); }
__device__ __forceinline__ void cp_wait0() { asm volatile("cp.async.wait_group 0;"); }
__device__ __forceinline__ void cp_wait1() { asm volatile("cp.async.wait_group 1;"); }

// ---------------------------------------------------------------------------
// Kernel 0: fused prep. Blocks [0,6144): X fp32->fp16. [6144,8192): W.
// [8192,8704): mask int32 -> bitmask (1 bit per element).
// ---------------------------------------------------------------------------
__global__ __launch_bounds__(256) void prep_all(
    const float* __restrict__ q, const float* __restrict__ k, const float* __restrict__ v,
    const float* __restrict__ wq, const float* __restrict__ wk, const float* __restrict__ wv,
    const float* __restrict__ wo, const int* __restrict__ mask)
{
    const int bb = blockIdx.x;
    if (bb >= 8192) {                       // mask -> bits
        int blk = bb - 8192;
        size_t base = ((size_t)blk * 256 + threadIdx.x) * 32;
        uint32_t bits = 0;
#pragma unroll
        for (int u = 0; u < 8; u++) {
            int4 m = *(const int4*)(mask + base + u * 4);
            bits |= (m.x ? 1u : 0u) << (u * 4 + 0);
            bits |= (m.y ? 1u : 0u) << (u * 4 + 1);
            bits |= (m.z ? 1u : 0u) << (u * 4 + 2);
            bits |= (m.w ? 1u : 0u) << (u * 4 + 3);
        }
        g_mbits[(size_t)blk * 256 + threadIdx.x] = bits;
        return;
    }
    const float* src; __half* dst; int inner;
    if (bb < 6144) {
        int which = bb >> 11;
        src = (which == 0) ? q : (which == 1) ? k : v;
        dst = (which == 0) ? g_xq : (which == 1) ? g_xk : g_xv;
        inner = bb & 2047;
    } else {
        int which = (bb - 6144) >> 9;
        src = (which == 0) ? wq : (which == 1) ? wk : (which == 2) ? wv : wo;
        dst = (which == 0) ? g_wq : (which == 1) ? g_wk : (which == 2) ? g_wv : g_wo;
        inner = (bb - 6144) & 511;
    }
    size_t i = (size_t)inner * 256 + threadIdx.x;
    float4 a = ((const float4*)src)[i * 2];
    float4 b = ((const float4*)src)[i * 2 + 1];
    uint4 o;
    o.x = h2u(__floats2half2_rn(a.x, a.y));
    o.y = h2u(__floats2half2_rn(a.z, a.w));
    o.z = h2u(__floats2half2_rn(b.x, b.y));
    o.w = h2u(__floats2half2_rn(b.z, b.w));
    ((uint4*)dst)[i] = o;
}

// ---------------------------------------------------------------------------
// Kernel 1: per-head projections. 512 threads (16 warps, 4x4), warp tile
// 32x32, BK=64, 3-stage cp.async ring. (at legacy-HMMA roofline; unchanged)
// ---------------------------------------------------------------------------
__global__ __launch_bounds__(512, 2) void proj_mma()
{
    const int which = blockIdx.z;
    const __half* X = (which == 0) ? g_xq : (which == 1) ? g_xk : g_xv;
    const __half* W = (which == 0) ? g_wq : (which == 1) ? g_wk : g_wv;
    __half* O       = (which == 0) ? g_qh : (which == 1) ? g_kh : g_vh;
    const int row0 = blockIdx.x * 128;
    const int col0 = blockIdx.y * 128;

    extern __shared__ __align__(16) __half sh[];
    __half* As = sh;                  // [3][128*72]
    __half* Bs = sh + 3 * 128 * 72;   // [3][64*136]
    const uint32_t sA = (uint32_t)__cvta_generic_to_shared(As);
    const uint32_t sB = (uint32_t)__cvta_generic_to_shared(Bs);
    const uint32_t ASZ = 128 * 72 * 2, BSZ = 64 * 136 * 2;

    const int t    = threadIdx.x;
    const int warp = t >> 5, lane = t & 31;
    const int gid  = lane >> 2, tig = lane & 3;
    const int wm   = warp >> 2;
    const int wn   = warp & 3;
    const int lr   = lane & 15;
    const int lc   = (lane >> 4) * 8;

    uint32_t aoffm[2], boffn[2];
#pragma unroll
    for (int mt = 0; mt < 2; mt++) aoffm[mt] = ((wm * 32 + mt * 16 + lr) * 72 + lc) * 2;
#pragma unroll
    for (int p = 0; p < 2; p++) boffn[p] = (lr * 136 + wn * 32 + p * 16 + lc) * 2;

    const __half* aptr[2]; uint32_t aoff[2];
    const __half* bptr[2]; uint32_t boff[2];
#pragma unroll
    for (int u = 0; u < 2; u++) {
        int c = t + u * 512;
        int arow = c >> 3, aseg = c & 7;
        aptr[u] = X + (size_t)(row0 + arow) * DM + aseg * 8;
        aoff[u] = (arow * 72 + aseg * 8) * 2;
        int brow = c >> 4, bseg = c & 15;
        int colh = col0 + bseg * 8, hh = colh >> 6, kk = colh & 63;
        bptr[u] = W + (size_t)hh * DM * DK + (size_t)brow * DK + kk;
        boff[u] = (brow * 136 + bseg * 8) * 2;
    }

    float acc[2][4][4] = {};
    const int NT = 16;

#pragma unroll
    for (int p = 0; p < 2; p++) {
#pragma unroll
        for (int u = 0; u < 2; u++) {
            cp16(sA + p * ASZ + aoff[u], aptr[u] + p * 64);
            cp16(sB + p * BSZ + boff[u], bptr[u] + (size_t)(p * 64) * DK);
        }
        cp_commit();
    }

    int slot = 0;
    for (int tt = 0; tt < NT; tt++) {
        cp_wait1();
        __syncthreads();

        if (tt + 2 < NT) {
            const int ps = (tt + 2) % 3;
            const int kt = (tt + 2) * 64;
#pragma unroll
            for (int u = 0; u < 2; u++) {
                cp16(sA + ps * ASZ + aoff[u], aptr[u] + kt);
                cp16(sB + ps * BSZ + boff[u], bptr[u] + (size_t)kt * DK);
            }
        }
        cp_commit();

        const uint32_t sAs = sA + slot * ASZ;
        const uint32_t sBs = sB + slot * BSZ;
#pragma unroll
        for (int ks = 0; ks < 4; ks++) {
            const int ko = ks * 16;
            uint32_t a[2][4], b[4][2];
#pragma unroll
            for (int mt = 0; mt < 2; mt++) ldsm4(a[mt], sAs + aoffm[mt] + ko * 2);
#pragma unroll
            for (int p = 0; p < 2; p++) {
                uint32_t r[4];
                ldsm4t(r, sBs + boffn[p] + ko * 136 * 2);
                b[p * 2][0] = r[0]; b[p * 2][1] = r[1];
                b[p * 2 + 1][0] = r[2]; b[p * 2 + 1][1] = r[3];
            }
#pragma unroll
            for (int mt = 0; mt < 2; mt++)
#pragma unroll
                for (int nt = 0; nt < 4; nt++) mma16(acc[mt][nt], a[mt], b[nt]);
        }
        slot = (slot + 1 == 3) ? 0 : slot + 1;
    }

#pragma unroll
    for (int mt = 0; mt < 2; mt++) {
        int r0 = row0 + wm * 32 + mt * 16 + gid;
        int bb = r0 >> 10, s0 = r0 & 1023;
#pragma unroll
        for (int nt = 0; nt < 4; nt++) {
            int col = col0 + wn * 32 + nt * 8 + 2 * tig;
            int hh = col >> 6, kk = col & 63;
            __half* base = O + (size_t)(hh * NB + bb) * SQ * DK;
            *(__half2*)(base + (size_t)s0 * DK + kk) =
                __floats2half2_rn(acc[mt][nt][0], acc[mt][nt][1]);
            *(__half2*)(base + (size_t)(s0 + 8) * DK + kk) =
                __floats2half2_rn(acc[mt][nt][2], acc[mt][nt][3]);
        }
    }
}

// ---------------------------------------------------------------------------
// Kernel 2: fused attention, register-resident P, 128-key outer tiles,
// BITMASK (one uint4 per row per 128-key tile instead of 32 int2 gmem loads).
// ---------------------------------------------------------------------------
__global__ __launch_bounds__(256, 2) void attn_mma(float* __restrict__ sc)
{
    extern __shared__ __align__(16) __half smh[];
    __half* Qs  = smh;                    // [128][72]
    __half* Ksm = Qs + 128 * 72;          // [2][128][72]
    __half* Vsm = Ksm + 2 * 128 * 72;     // [2][128][72]

    const uint32_t qsm = (uint32_t)__cvta_generic_to_shared(Qs);
    const uint32_t ksm = (uint32_t)__cvta_generic_to_shared(Ksm);
    const uint32_t vsm = (uint32_t)__cvta_generic_to_shared(Vsm);
    const uint32_t TSZ = 128 * 72 * 2;
    const uint32_t HSZ = 64 * 72 * 2;

    const int hb = blockIdx.y;
    const int h  = hb >> 2, b = hb & 3;
    const int q0 = blockIdx.x * 128;
    const int t = threadIdx.x, warp = t >> 5, lane = t & 31;
    const int gid = lane >> 2, tig = lane & 3;
    const int lr = lane & 15;
    const int lc = (lane >> 4) * 8;

    const __half* qbase = g_qh + ((size_t)hb * SQ + q0) * DK;
    const __half* kbase = g_kh + (size_t)hb * SQ * DK;
    const __half* vbase = g_vh + (size_t)hb * SQ * DK;

    const uint32_t qoff = ((warp * 16 + lr) * 72 + lc) * 2;
    uint32_t koff[4], voff[4];
#pragma unroll
    for (int p = 0; p < 4; p++) {
        koff[p] = ((p * 16 + ((lane >> 4) & 1) * 8 + (lane & 7)) * 72
                   + ((lane >> 3) & 1) * 8) * 2;
        voff[p] = (lr * 72 + p * 16 + lc) * 2;
    }

#pragma unroll
    for (int u = 0; u < 4; u++) {
        int c = t + u * 256;
        int row = c >> 3, seg = c & 7;
        cp16(qsm + (row * 72 + seg * 8) * 2, qbase + (size_t)row * DK + seg * 8);
        cp16(ksm + (row * 72 + seg * 8) * 2, kbase + (size_t)row * DK + seg * 8);
        cp16(vsm + (row * 72 + seg * 8) * 2, vbase + (size_t)row * DK + seg * 8);
    }
    cp_commit();
    cp_wait0();
    __syncthreads();

    uint32_t qf[4][4];
#pragma unroll
    for (int j = 0; j < 4; j++) ldsm4(qf[j], qsm + qoff + j * 16 * 2);

    float Oacc[8][4] = {};
    float rs0 = 0.f, rs1 = 0.f;
    const float NEGINF = __int_as_float(0xff800000u);

    const int rl0 = warp * 16 + gid;
    const int rl1 = rl0 + 8;
    // bitmask rows: 32 uint32 per row; one uint4 covers 128 keys
    const uint4* mb0 = (const uint4*)(g_mbits + ((size_t)b * SQ + q0 + rl0) * 32);
    const uint4* mb1 = (const uint4*)(g_mbits + ((size_t)b * SQ + q0 + rl1) * 32);
    float* srow0 = sc + ((size_t)hb * SQ + q0 + rl0) * SQ;
    float* srow1 = sc + ((size_t)hb * SQ + q0 + rl1) * SQ;

    for (int kb = 0; kb < 8; kb++) {
        const int slot = kb & 1;
        if (kb > 0) { cp_wait0(); __syncthreads(); }
        if (kb + 1 < 8) {
            const int so = slot ^ 1;
            const __half* kp = kbase + (size_t)(kb + 1) * 128 * DK;
            const __half* vp = vbase + (size_t)(kb + 1) * 128 * DK;
#pragma unroll
            for (int u = 0; u < 4; u++) {
                int c = t + u * 256;
                int row = c >> 3, seg = c & 7;
                cp16(ksm + so * TSZ + (row * 72 + seg * 8) * 2, kp + (size_t)row * DK + seg * 8);
                cp16(vsm + so * TSZ + (row * 72 + seg * 8) * 2, vp + (size_t)row * DK + seg * 8);
            }
        }
        cp_commit();

        // mask bits for this 128-key tile (2 loads replace 32 int2 loads)
        uint4 w0v = mb0[kb];
        uint4 w1v = mb1[kb];
        uint32_t mw0[4] = {w0v.x, w0v.y, w0v.z, w0v.w};
        uint32_t mw1[4] = {w1v.x, w1v.y, w1v.z, w1v.w};

        const uint32_t Kp = ksm + slot * TSZ;
        const uint32_t Vp = vsm + slot * TSZ;

#pragma unroll
        for (int hf = 0; hf < 2; hf++) {
            const uint32_t Kph = Kp + hf * HSZ;
            const uint32_t Vph = Vp + hf * HSZ;

            float Sacc[8][4] = {};
            {
                uint32_t bk[2][8][2];
#pragma unroll
                for (int p = 0; p < 4; p++) {
                    uint32_t r[4];
                    ldsm4(r, Kph + koff[p]);
                    bk[0][p * 2][0] = r[0]; bk[0][p * 2][1] = r[1];
                    bk[0][p * 2 + 1][0] = r[2]; bk[0][p * 2 + 1][1] = r[3];
                }
#pragma unroll
                for (int j = 0; j < 4; j++) {
                    const int cur = j & 1, nxt = cur ^ 1;
                    if (j < 3) {
#pragma unroll
                        for (int p = 0; p < 4; p++) {
                            uint32_t r[4];
                            ldsm4(r, Kph + koff[p] + (j + 1) * 16 * 2);
                            bk[nxt][p * 2][0] = r[0]; bk[nxt][p * 2][1] = r[1];
                            bk[nxt][p * 2 + 1][0] = r[2]; bk[nxt][p * 2 + 1][1] = r[3];
                        }
                    }
#pragma unroll
                    for (int nt = 0; nt < 8; nt++) mma16(Sacc[nt], qf[j], bk[cur][nt]);
                }
            }

            uint32_t apv[4][4];
            const int cb = kb * 128 + hf * 64;
#pragma unroll
            for (int nt = 0; nt < 8; nt++) {
                int cl = cb + nt * 8 + 2 * tig;
                const int word = hf * 2 + (nt >> 2);           // compile-time
                const int bit = (nt & 3) * 8 + 2 * tig;        // runtime tig only
                uint32_t b0 = mw0[word] >> bit;
                uint32_t b1 = mw1[word] >> bit;
                float s00 = (b0 & 1u) ? Sacc[nt][0] * 0.125f : NEGINF;
                float s01 = (b0 & 2u) ? Sacc[nt][1] * 0.125f : NEGINF;
                float s10 = (b1 & 1u) ? Sacc[nt][2] * 0.125f : NEGINF;
                float s11 = (b1 & 2u) ? Sacc[nt][3] * 0.125f : NEGINF;
                __stcs((float2*)(srow0 + cl), make_float2(s00, s01));
                __stcs((float2*)(srow1 + cl), make_float2(s10, s11));
                float e00 = __expf(s00), e01 = __expf(s01);
                float e10 = __expf(s10), e11 = __expf(s11);
                rs0 += e00 + e01;
                rs1 += e10 + e11;
                int j = nt >> 1;
                if ((nt & 1) == 0) {
                    apv[j][0] = h2u(__floats2half2_rn(e00, e01));
                    apv[j][1] = h2u(__floats2half2_rn(e10, e11));
                } else {
                    apv[j][2] = h2u(__floats2half2_rn(e00, e01));
                    apv[j][3] = h2u(__floats2half2_rn(e10, e11));
                }
            }

            {
                uint32_t bv[2][8][2];
#pragma unroll
                for (int p = 0; p < 4; p++) {
                    uint32_t r[4];
                    ldsm4t(r, Vph + voff[p]);
                    bv[0][p * 2][0] = r[0]; bv[0][p * 2][1] = r[1];
                    bv[0][p * 2 + 1][0] = r[2]; bv[0][p * 2 + 1][1] = r[3];
                }
#pragma unroll
                for (int j = 0; j < 4; j++) {
                    const int cur = j & 1, nxt = cur ^ 1;
                    if (j < 3) {
#pragma unroll
                        for (int p = 0; p < 4; p++) {
                            uint32_t r[4];
                            ldsm4t(r, Vph + voff[p] + (j + 1) * 16 * 72 * 2);
                            bv[nxt][p * 2][0] = r[0]; bv[nxt][p * 2][1] = r[1];
                            bv[nxt][p * 2 + 1][0] = r[2]; bv[nxt][p * 2 + 1][1] = r[3];
                        }
                    }
#pragma unroll
                    for (int nt = 0; nt < 8; nt++) mma16(Oacc[nt], apv[j], bv[cur][nt]);
                }
            }
        }
    }

    rs0 += __shfl_xor_sync(0xffffffffu, rs0, 1);
    rs0 += __shfl_xor_sync(0xffffffffu, rs0, 2);
    rs1 += __shfl_xor_sync(0xffffffffu, rs1, 1);
    rs1 += __shfl_xor_sync(0xffffffffu, rs1, 2);
    float inv0 = 1.0f / rs0, inv1 = 1.0f / rs1;

    __half* c0 = g_ch + ((size_t)b * SQ + q0 + rl0) * DM + h * DK;
    __half* c1 = g_ch + ((size_t)b * SQ + q0 + rl1) * DM + h * DK;
#pragma unroll
    for (int nt = 0; nt < 8; nt++) {
        int cl = nt * 8 + 2 * tig;
        *(__half2*)(c0 + cl) = __floats2half2_rn(Oacc[nt][0] * inv0, Oacc[nt][1] * inv0);
        *(__half2*)(c1 + cl) = __floats2half2_rn(Oacc[nt][2] * inv1, Oacc[nt][3] * inv1);
    }
}

// ---------------------------------------------------------------------------
// Kernel 3: out = concat @ Wo. 512 threads, 4x4 warps, BK=64, 3-stage. fp32 out.
// (at legacy-HMMA roofline; unchanged)
// ---------------------------------------------------------------------------
__global__ __launch_bounds__(512, 2) void outproj_mma(float* __restrict__ out)
{
    const int row0 = blockIdx.x * 128;
    const int col0 = blockIdx.y * 128;

    extern __shared__ __align__(16) __half sh[];
    __half* As = sh;
    __half* Bs = sh + 3 * 128 * 72;
    const uint32_t sA = (uint32_t)__cvta_generic_to_shared(As);
    const uint32_t sB = (uint32_t)__cvta_generic_to_shared(Bs);
    const uint32_t ASZ = 128 * 72 * 2, BSZ = 64 * 136 * 2;

    const int t    = threadIdx.x;
    const int warp = t >> 5, lane = t & 31;
    const int gid  = lane >> 2, tig = lane & 3;
    const int wm   = warp >> 2;
    const int wn   = warp & 3;
    const int lr   = lane & 15;
    const int lc   = (lane >> 4) * 8;

    uint32_t aoffm[2], boffn[2];
#pragma unroll
    for (int mt = 0; mt < 2; mt++) aoffm[mt] = ((wm * 32 + mt * 16 + lr) * 72 + lc) * 2;
#pragma unroll
    for (int p = 0; p < 2; p++) boffn[p] = (lr * 136 + wn * 32 + p * 16 + lc) * 2;

    const __half* aptr[2]; uint32_t aoff[2];
    const __half* bptr[2]; uint32_t boff[2];
#pragma unroll
    for (int u = 0; u < 2; u++) {
        int c = t + u * 512;
        int arow = c >> 3, aseg = c & 7;
        aptr[u] = g_ch + (size_t)(row0 + arow) * DM + aseg * 8;
        aoff[u] = (arow * 72 + aseg * 8) * 2;
        int brow = c >> 4, bseg = c & 15;
        bptr[u] = g_wo + (size_t)brow * DM + col0 + bseg * 8;
        boff[u] = (brow * 136 + bseg * 8) * 2;
    }

    float acc[2][4][4] = {};
    const int NT = 16;

#pragma unroll
    for (int p = 0; p < 2; p++) {
#pragma unroll
        for (int u = 0; u < 2; u++) {
            cp16(sA + p * ASZ + aoff[u], aptr[u] + p * 64);
            cp16(sB + p * BSZ + boff[u], bptr[u] + (size_t)(p * 64) * DM);
        }
        cp_commit();
    }

    int slot = 0;
    for (int tt = 0; tt < NT; tt++) {
        cp_wait1();
        __syncthreads();

        if (tt + 2 < NT) {
            const int ps = (tt + 2) % 3;
            const int kt = (tt + 2) * 64;
#pragma unroll
            for (int u = 0; u < 2; u++) {
                cp16(sA + ps * ASZ + aoff[u], aptr[u] + kt);
                cp16(sB + ps * BSZ + boff[u], bptr[u] + (size_t)kt * DM);
            }
        }
        cp_commit();

        const uint32_t sAs = sA + slot * ASZ;
        const uint32_t sBs = sB + slot * BSZ;
#pragma unroll
        for (int ks = 0; ks < 4; ks++) {
            const int ko = ks * 16;
            uint32_t a[2][4], b[4][2];
#pragma unroll
            for (int mt = 0; mt < 2; mt++) ldsm4(a[mt], sAs + aoffm[mt] + ko * 2);
#pragma unroll
            for (int p = 0; p < 2; p++) {
                uint32_t r[4];
                ldsm4t(r, sBs + boffn[p] + ko * 136 * 2);
                b[p * 2][0] = r[0]; b[p * 2][1] = r[1];
                b[p * 2 + 1][0] = r[2]; b[p * 2 + 1][1] = r[3];
            }
#pragma unroll
            for (int mt = 0; mt < 2; mt++)
#pragma unroll
                for (int nt = 0; nt < 4; nt++) mma16(acc[mt][nt], a[mt], b[nt]);
        }
        slot = (slot + 1 == 3) ? 0 : slot + 1;
    }

#pragma unroll
    for (int mt = 0; mt < 2; mt++) {
        int r = row0 + wm * 32 + mt * 16 + gid;
#pragma unroll
        for (int nt = 0; nt < 4; nt++) {
            int col = col0 + wn * 32 + nt * 8 + 2 * tig;
            *(float2*)(out + (size_t)r * DM + col)       = make_float2(acc[mt][nt][0], acc[mt][nt][1]);
            *(float2*)(out + (size_t)(r + 8) * DM + col) = make_float2(acc[mt][nt][2], acc[mt][nt][3]);
        }
    }
}

// ---------------------------------------------------------------------------
extern "C" void kernel_launch(void* const* d_in, const int* in_sizes, int n_in,
                              void* d_out, int out_size)
{
    const float* q    = (const float*)d_in[0];
    const float* k    = (const float*)d_in[1];
    const float* v    = (const float*)d_in[2];
    const int*   mask = (const int*)  d_in[3];
    const float* Wq   = (const float*)d_in[4];
    const float* Wk   = (const float*)d_in[5];
    const float* Wv   = (const float*)d_in[6];
    const float* Wo   = (const float*)d_in[7];

    float* out = (float*)d_out;
    float* scp = out + (size_t)MR * DM;

    static int smem_set = 0;
    if (!smem_set) {
        cudaFuncSetAttribute(proj_mma,    cudaFuncAttributeMaxDynamicSharedMemorySize, 107520);
        cudaFuncSetAttribute(outproj_mma, cudaFuncAttributeMaxDynamicSharedMemorySize, 107520);
        cudaFuncSetAttribute(attn_mma,    cudaFuncAttributeMaxDynamicSharedMemorySize, 92160);
        smem_set = 1;
    }

    prep_all   <<<8704, 256>>>(q, k, v, Wq, Wk, Wv, Wo, mask);
    proj_mma   <<<dim3(32, 8, 3), 512, 107520>>>();
    attn_mma   <<<dim3(8, 64), 256, 92160>>>(scp);
    outproj_mma<<<dim3(32, 8), 512, 107520>>>(out);
}

// round 14
// speedup vs baseline: 1.1704x; 1.0036x over previous
#include <cuda_runtime.h>
#include <cuda_fp16.h>
#include <cstdint>

#define NH 16
#define NB 4
#define SQ 1024
#define DM 1024
#define DK 64
#define MR (NB * SQ)
#define HB (NH * NB)

// fp16 scratch (__device__ globals per allocation-free rule)
__device__ __half g_xq[(size_t)MR * DM];
__device__ __half g_xk[(size_t)MR * DM];
__device__ __half g_xv[(size_t)MR * DM];
__device__ __half g_wq[(size_t)NH * DM * DK];
__device__ __half g_wk[(size_t)NH * DM * DK];
__device__ __half g_wv[(size_t)NH * DM * DK];
__device__ __half g_wo[(size_t)DM * DM];
__device__ __half g_qh[(size_t)HB * SQ * DK];
__device__ __half g_kh[(size_t)HB * SQ * DK];
__device__ __half g_vh[(size_t)HB * SQ * DK];
__device__ __half g_ch[(size_t)MR * DM];
__device__ uint32_t g_mbits[(size_t)NB * SQ * (SQ / 32)];   // 1 bit per mask elem

__device__ __forceinline__ uint32_t h2u(__half2 h) { return *(uint32_t*)&h; }

__device__ __forceinline__ void ldsm4(uint32_t* r, uint32_t addr) {
    asm volatile("ldmatrix.sync.aligned.m8n8.x4.shared.b16 {%0,%1,%2,%3}, [%4];"
        : "=r"(r[0]), "=r"(r[1]), "=r"(r[2]), "=r"(r[3]) : "r"(addr));
}
__device__ __forceinline__ void ldsm4t(uint32_t* r, uint32_t addr) {
    asm volatile("ldmatrix.sync.aligned.m8n8.x4.trans.shared.b16 {%0,%1,%2,%3}, [%4];"
        : "=r"(r[0]), "=r"(r[1]), "=r"(r[2]), "=r"(r[3]) : "r"(addr));
}
__device__ __forceinline__ void mma16(float* d, const uint32_t* a, const uint32_t* b) {
    asm volatile("mma.sync.aligned.m16n8k16.row.col.f32.f16.f16.f32 "
        "{%0,%1,%2,%3}, {%4,%5,%6,%7}, {%8,%9}, {%0,%1,%2,%3};"
        : "+f"(d[0]), "+f"(d[1]), "+f"(d[2]), "+f"(d[3])
        : "r"(a[0]), "r"(a[1]), "r"(a[2]), "r"(a[3]), "r"(b[0]), "r"(b[1]));
}
__device__ __forceinline__ void cp16(uint32_t dst, const void* src) {
    asm volatile("cp.async.cg.shared.global [%0], [%1], 16;" :: "r"(dst), "l"(src));
}
__device__ __forceinline__ void cp_commit() { asm volatile("cp.async.commit_group;"); }
__device__ __forceinline__ void cp_wait0() { asm volatile("cp.async.wait_group 0;"); }
__device__ __forceinline__ void cp_wait1() { asm volatile("cp.async.wait_group 1;"); }

// ---------------------------------------------------------------------------
// Kernel 0: fused prep. Blocks [0,6144): X fp32->fp16. [6144,8192): W.
// [8192,8704): mask int32 -> bitmask.
// ---------------------------------------------------------------------------
__global__ __launch_bounds__(256) void prep_all(
    const float* __restrict__ q, const float* __restrict__ k, const float* __restrict__ v,
    const float* __restrict__ wq, const float* __restrict__ wk, const float* __restrict__ wv,
    const float* __restrict__ wo, const int* __restrict__ mask)
{
    const int bb = blockIdx.x;
    if (bb >= 8192) {                       // mask -> bits
        int blk = bb - 8192;
        size_t base = ((size_t)blk * 256 + threadIdx.x) * 32;
        uint32_t bits = 0;
#pragma unroll
        for (int u = 0; u < 8; u++) {
            int4 m = *(const int4*)(mask + base + u * 4);
            bits |= (m.x ? 1u : 0u) << (u * 4 + 0);
            bits |= (m.y ? 1u : 0u) << (u * 4 + 1);
            bits |= (m.z ? 1u : 0u) << (u * 4 + 2);
            bits |= (m.w ? 1u : 0u) << (u * 4 + 3);
        }
        g_mbits[(size_t)blk * 256 + threadIdx.x] = bits;
        return;
    }
    const float* src; __half* dst; int inner;
    if (bb < 6144) {
        int which = bb >> 11;
        src = (which == 0) ? q : (which == 1) ? k : v;
        dst = (which == 0) ? g_xq : (which == 1) ? g_xk : g_xv;
        inner = bb & 2047;
    } else {
        int which = (bb - 6144) >> 9;
        src = (which == 0) ? wq : (which == 1) ? wk : (which == 2) ? wv : wo;
        dst = (which == 0) ? g_wq : (which == 1) ? g_wk : (which == 2) ? g_wv : g_wo;
        inner = (bb - 6144) & 511;
    }
    size_t i = (size_t)inner * 256 + threadIdx.x;
    float4 a = ((const float4*)src)[i * 2];
    float4 b = ((const float4*)src)[i * 2 + 1];
    uint4 o;
    o.x = h2u(__floats2half2_rn(a.x, a.y));
    o.y = h2u(__floats2half2_rn(a.z, a.w));
    o.z = h2u(__floats2half2_rn(b.x, b.y));
    o.w = h2u(__floats2half2_rn(b.z, b.w));
    ((uint4*)dst)[i] = o;
}

// ---------------------------------------------------------------------------
// Kernel 1: per-head projections. 512 threads (16 warps, 4x4), warp tile
// 32x32, BK=64, 3-stage cp.async ring. (at legacy-HMMA roofline; unchanged)
// ---------------------------------------------------------------------------
__global__ __launch_bounds__(512, 2) void proj_mma()
{
    const int which = blockIdx.z;
    const __half* X = (which == 0) ? g_xq : (which == 1) ? g_xk : g_xv;
    const __half* W = (which == 0) ? g_wq : (which == 1) ? g_wk : g_wv;
    __half* O       = (which == 0) ? g_qh : (which == 1) ? g_kh : g_vh;
    const int row0 = blockIdx.x * 128;
    const int col0 = blockIdx.y * 128;

    extern __shared__ __align__(16) __half sh[];
    __half* As = sh;                  // [3][128*72]
    __half* Bs = sh + 3 * 128 * 72;   // [3][64*136]
    const uint32_t sA = (uint32_t)__cvta_generic_to_shared(As);
    const uint32_t sB = (uint32_t)__cvta_generic_to_shared(Bs);
    const uint32_t ASZ = 128 * 72 * 2, BSZ = 64 * 136 * 2;

    const int t    = threadIdx.x;
    const int warp = t >> 5, lane = t & 31;
    const int gid  = lane >> 2, tig = lane & 3;
    const int wm   = warp >> 2;
    const int wn   = warp & 3;
    const int lr   = lane & 15;
    const int lc   = (lane >> 4) * 8;

    uint32_t aoffm[2], boffn[2];
#pragma unroll
    for (int mt = 0; mt < 2; mt++) aoffm[mt] = ((wm * 32 + mt * 16 + lr) * 72 + lc) * 2;
#pragma unroll
    for (int p = 0; p < 2; p++) boffn[p] = (lr * 136 + wn * 32 + p * 16 + lc) * 2;

    const __half* aptr[2]; uint32_t aoff[2];
    const __half* bptr[2]; uint32_t boff[2];
#pragma unroll
    for (int u = 0; u < 2; u++) {
        int c = t + u * 512;
        int arow = c >> 3, aseg = c & 7;
        aptr[u] = X + (size_t)(row0 + arow) * DM + aseg * 8;
        aoff[u] = (arow * 72 + aseg * 8) * 2;
        int brow = c >> 4, bseg = c & 15;
        int colh = col0 + bseg * 8, hh = colh >> 6, kk = colh & 63;
        bptr[u] = W + (size_t)hh * DM * DK + (size_t)brow * DK + kk;
        boff[u] = (brow * 136 + bseg * 8) * 2;
    }

    float acc[2][4][4] = {};
    const int NT = 16;

#pragma unroll
    for (int p = 0; p < 2; p++) {
#pragma unroll
        for (int u = 0; u < 2; u++) {
            cp16(sA + p * ASZ + aoff[u], aptr[u] + p * 64);
            cp16(sB + p * BSZ + boff[u], bptr[u] + (size_t)(p * 64) * DK);
        }
        cp_commit();
    }

    int slot = 0;
    for (int tt = 0; tt < NT; tt++) {
        cp_wait1();
        __syncthreads();

        if (tt + 2 < NT) {
            const int ps = (tt + 2) % 3;
            const int kt = (tt + 2) * 64;
#pragma unroll
            for (int u = 0; u < 2; u++) {
                cp16(sA + ps * ASZ + aoff[u], aptr[u] + kt);
                cp16(sB + ps * BSZ + boff[u], bptr[u] + (size_t)kt * DK);
            }
        }
        cp_commit();

        const uint32_t sAs = sA + slot * ASZ;
        const uint32_t sBs = sB + slot * BSZ;
#pragma unroll
        for (int ks = 0; ks < 4; ks++) {
            const int ko = ks * 16;
            uint32_t a[2][4], b[4][2];
#pragma unroll
            for (int mt = 0; mt < 2; mt++) ldsm4(a[mt], sAs + aoffm[mt] + ko * 2);
#pragma unroll
            for (int p = 0; p < 2; p++) {
                uint32_t r[4];
                ldsm4t(r, sBs + boffn[p] + ko * 136 * 2);
                b[p * 2][0] = r[0]; b[p * 2][1] = r[1];
                b[p * 2 + 1][0] = r[2]; b[p * 2 + 1][1] = r[3];
            }
#pragma unroll
            for (int mt = 0; mt < 2; mt++)
#pragma unroll
                for (int nt = 0; nt < 4; nt++) mma16(acc[mt][nt], a[mt], b[nt]);
        }
        slot = (slot + 1 == 3) ? 0 : slot + 1;
    }

#pragma unroll
    for (int mt = 0; mt < 2; mt++) {
        int r0 = row0 + wm * 32 + mt * 16 + gid;
        int bb = r0 >> 10, s0 = r0 & 1023;
#pragma unroll
        for (int nt = 0; nt < 4; nt++) {
            int col = col0 + wn * 32 + nt * 8 + 2 * tig;
            int hh = col >> 6, kk = col & 63;
            __half* base = O + (size_t)(hh * NB + bb) * SQ * DK;
            *(__half2*)(base + (size_t)s0 * DK + kk) =
                __floats2half2_rn(acc[mt][nt][0], acc[mt][nt][1]);
            *(__half2*)(base + (size_t)(s0 + 8) * DK + kk) =
                __floats2half2_rn(acc[mt][nt][2], acc[mt][nt][3]);
        }
    }
}

// ---------------------------------------------------------------------------
// Kernel 2: fused attention. Register-resident P, 128-key outer tiles,
// bitmask. NEW: softmax epilogue interleaved with PV mma per k16 step j —
// exp/stores for score fragments 2j,2j+1 issue between tensor ops.
// ---------------------------------------------------------------------------
__global__ __launch_bounds__(256, 2) void attn_mma(float* __restrict__ sc)
{
    extern __shared__ __align__(16) __half smh[];
    __half* Qs  = smh;                    // [128][72]
    __half* Ksm = Qs + 128 * 72;          // [2][128][72]
    __half* Vsm = Ksm + 2 * 128 * 72;     // [2][128][72]

    const uint32_t qsm = (uint32_t)__cvta_generic_to_shared(Qs);
    const uint32_t ksm = (uint32_t)__cvta_generic_to_shared(Ksm);
    const uint32_t vsm = (uint32_t)__cvta_generic_to_shared(Vsm);
    const uint32_t TSZ = 128 * 72 * 2;
    const uint32_t HSZ = 64 * 72 * 2;

    const int hb = blockIdx.y;
    const int h  = hb >> 2, b = hb & 3;
    const int q0 = blockIdx.x * 128;
    const int t = threadIdx.x, warp = t >> 5, lane = t & 31;
    const int gid = lane >> 2, tig = lane & 3;
    const int lr = lane & 15;
    const int lc = (lane >> 4) * 8;

    const __half* qbase = g_qh + ((size_t)hb * SQ + q0) * DK;
    const __half* kbase = g_kh + (size_t)hb * SQ * DK;
    const __half* vbase = g_vh + (size_t)hb * SQ * DK;

    const uint32_t qoff = ((warp * 16 + lr) * 72 + lc) * 2;
    uint32_t koff[4], voff[4];
#pragma unroll
    for (int p = 0; p < 4; p++) {
        koff[p] = ((p * 16 + ((lane >> 4) & 1) * 8 + (lane & 7)) * 72
                   + ((lane >> 3) & 1) * 8) * 2;
        voff[p] = (lr * 72 + p * 16 + lc) * 2;
    }

#pragma unroll
    for (int u = 0; u < 4; u++) {
        int c = t + u * 256;
        int row = c >> 3, seg = c & 7;
        cp16(qsm + (row * 72 + seg * 8) * 2, qbase + (size_t)row * DK + seg * 8);
        cp16(ksm + (row * 72 + seg * 8) * 2, kbase + (size_t)row * DK + seg * 8);
        cp16(vsm + (row * 72 + seg * 8) * 2, vbase + (size_t)row * DK + seg * 8);
    }
    cp_commit();
    cp_wait0();
    __syncthreads();

    uint32_t qf[4][4];
#pragma unroll
    for (int j = 0; j < 4; j++) ldsm4(qf[j], qsm + qoff + j * 16 * 2);

    float Oacc[8][4] = {};
    float rs0 = 0.f, rs1 = 0.f;
    const float NEGINF = __int_as_float(0xff800000u);

    const int rl0 = warp * 16 + gid;
    const int rl1 = rl0 + 8;
    const uint4* mb0 = (const uint4*)(g_mbits + ((size_t)b * SQ + q0 + rl0) * 32);
    const uint4* mb1 = (const uint4*)(g_mbits + ((size_t)b * SQ + q0 + rl1) * 32);
    float* srow0 = sc + ((size_t)hb * SQ + q0 + rl0) * SQ;
    float* srow1 = sc + ((size_t)hb * SQ + q0 + rl1) * SQ;

    for (int kb = 0; kb < 8; kb++) {
        const int slot = kb & 1;
        if (kb > 0) { cp_wait0(); __syncthreads(); }
        if (kb + 1 < 8) {
            const int so = slot ^ 1;
            const __half* kp = kbase + (size_t)(kb + 1) * 128 * DK;
            const __half* vp = vbase + (size_t)(kb + 1) * 128 * DK;
#pragma unroll
            for (int u = 0; u < 4; u++) {
                int c = t + u * 256;
                int row = c >> 3, seg = c & 7;
                cp16(ksm + so * TSZ + (row * 72 + seg * 8) * 2, kp + (size_t)row * DK + seg * 8);
                cp16(vsm + so * TSZ + (row * 72 + seg * 8) * 2, vp + (size_t)row * DK + seg * 8);
            }
        }
        cp_commit();

        uint4 w0v = mb0[kb];
        uint4 w1v = mb1[kb];
        uint32_t mw0[4] = {w0v.x, w0v.y, w0v.z, w0v.w};
        uint32_t mw1[4] = {w1v.x, w1v.y, w1v.z, w1v.w};

        const uint32_t Kp = ksm + slot * TSZ;
        const uint32_t Vp = vsm + slot * TSZ;

#pragma unroll
        for (int hf = 0; hf < 2; hf++) {
            const uint32_t Kph = Kp + hf * HSZ;
            const uint32_t Vph = Vp + hf * HSZ;

            // S = Q @ K^T : depth-2 pipelined over j
            float Sacc[8][4] = {};
            {
                uint32_t bk[2][8][2];
#pragma unroll
                for (int p = 0; p < 4; p++) {
                    uint32_t r[4];
                    ldsm4(r, Kph + koff[p]);
                    bk[0][p * 2][0] = r[0]; bk[0][p * 2][1] = r[1];
                    bk[0][p * 2 + 1][0] = r[2]; bk[0][p * 2 + 1][1] = r[3];
                }
#pragma unroll
                for (int j = 0; j < 4; j++) {
                    const int cur = j & 1, nxt = cur ^ 1;
                    if (j < 3) {
#pragma unroll
                        for (int p = 0; p < 4; p++) {
                            uint32_t r[4];
                            ldsm4(r, Kph + koff[p] + (j + 1) * 16 * 2);
                            bk[nxt][p * 2][0] = r[0]; bk[nxt][p * 2][1] = r[1];
                            bk[nxt][p * 2 + 1][0] = r[2]; bk[nxt][p * 2 + 1][1] = r[3];
                        }
                    }
#pragma unroll
                    for (int nt = 0; nt < 8; nt++) mma16(Sacc[nt], qf[j], bk[cur][nt]);
                }
            }

            // interleaved: epilogue for nt=2j,2j+1 -> apv, then PV mma step j
            const int cb = kb * 128 + hf * 64;
#pragma unroll
            for (int j = 0; j < 4; j++) {
                uint32_t apv[4];
#pragma unroll
                for (int e = 0; e < 2; e++) {
                    const int nt = 2 * j + e;
                    int cl = cb + nt * 8 + 2 * tig;
                    const int word = hf * 2 + (nt >> 2);       // compile-time
                    const int bit = (nt & 3) * 8 + 2 * tig;
                    uint32_t b0 = mw0[word] >> bit;
                    uint32_t b1 = mw1[word] >> bit;
                    float s00 = (b0 & 1u) ? Sacc[nt][0] * 0.125f : NEGINF;
                    float s01 = (b0 & 2u) ? Sacc[nt][1] * 0.125f : NEGINF;
                    float s10 = (b1 & 1u) ? Sacc[nt][2] * 0.125f : NEGINF;
                    float s11 = (b1 & 2u) ? Sacc[nt][3] * 0.125f : NEGINF;
                    __stcs((float2*)(srow0 + cl), make_float2(s00, s01));
                    __stcs((float2*)(srow1 + cl), make_float2(s10, s11));
                    float e00 = __expf(s00), e01 = __expf(s01);
                    float e10 = __expf(s10), e11 = __expf(s11);
                    rs0 += e00 + e01;
                    rs1 += e10 + e11;
                    if (e == 0) {
                        apv[0] = h2u(__floats2half2_rn(e00, e01));
                        apv[1] = h2u(__floats2half2_rn(e10, e11));
                    } else {
                        apv[2] = h2u(__floats2half2_rn(e00, e01));
                        apv[3] = h2u(__floats2half2_rn(e10, e11));
                    }
                }
                uint32_t bv[8][2];
#pragma unroll
                for (int p = 0; p < 4; p++) {
                    uint32_t r[4];
                    ldsm4t(r, Vph + voff[p] + j * 16 * 72 * 2);
                    bv[p * 2][0] = r[0]; bv[p * 2][1] = r[1];
                    bv[p * 2 + 1][0] = r[2]; bv[p * 2 + 1][1] = r[3];
                }
#pragma unroll
                for (int nt = 0; nt < 8; nt++) mma16(Oacc[nt], apv, bv[nt]);
            }
        }
    }

    rs0 += __shfl_xor_sync(0xffffffffu, rs0, 1);
    rs0 += __shfl_xor_sync(0xffffffffu, rs0, 2);
    rs1 += __shfl_xor_sync(0xffffffffu, rs1, 1);
    rs1 += __shfl_xor_sync(0xffffffffu, rs1, 2);
    float inv0 = 1.0f / rs0, inv1 = 1.0f / rs1;

    __half* c0 = g_ch + ((size_t)b * SQ + q0 + rl0) * DM + h * DK;
    __half* c1 = g_ch + ((size_t)b * SQ + q0 + rl1) * DM + h * DK;
#pragma unroll
    for (int nt = 0; nt < 8; nt++) {
        int cl = nt * 8 + 2 * tig;
        *(__half2*)(c0 + cl) = __floats2half2_rn(Oacc[nt][0] * inv0, Oacc[nt][1] * inv0);
        *(__half2*)(c1 + cl) = __floats2half2_rn(Oacc[nt][2] * inv1, Oacc[nt][3] * inv1);
    }
}

// ---------------------------------------------------------------------------
// Kernel 3: out = concat @ Wo. 512 threads, 4x4 warps, BK=64, 3-stage.
// (at legacy-HMMA roofline; unchanged)
// ---------------------------------------------------------------------------
__global__ __launch_bounds__(512, 2) void outproj_mma(float* __restrict__ out)
{
    const int row0 = blockIdx.x * 128;
    const int col0 = blockIdx.y * 128;

    extern __shared__ __align__(16) __half sh[];
    __half* As = sh;
    __half* Bs = sh + 3 * 128 * 72;
    const uint32_t sA = (uint32_t)__cvta_generic_to_shared(As);
    const uint32_t sB = (uint32_t)__cvta_generic_to_shared(Bs);
    const uint32_t ASZ = 128 * 72 * 2, BSZ = 64 * 136 * 2;

    const int t    = threadIdx.x;
    const int warp = t >> 5, lane = t & 31;
    const int gid  = lane >> 2, tig = lane & 3;
    const int wm   = warp >> 2;
    const int wn   = warp & 3;
    const int lr   = lane & 15;
    const int lc   = (lane >> 4) * 8;

    uint32_t aoffm[2], boffn[2];
#pragma unroll
    for (int mt = 0; mt < 2; mt++) aoffm[mt] = ((wm * 32 + mt * 16 + lr) * 72 + lc) * 2;
#pragma unroll
    for (int p = 0; p < 2; p++) boffn[p] = (lr * 136 + wn * 32 + p * 16 + lc) * 2;

    const __half* aptr[2]; uint32_t aoff[2];
    const __half* bptr[2]; uint32_t boff[2];
#pragma unroll
    for (int u = 0; u < 2; u++) {
        int c = t + u * 512;
        int arow = c >> 3, aseg = c & 7;
        aptr[u] = g_ch + (size_t)(row0 + arow) * DM + aseg * 8;
        aoff[u] = (arow * 72 + aseg * 8) * 2;
        int brow = c >> 4, bseg = c & 15;
        bptr[u] = g_wo + (size_t)brow * DM + col0 + bseg * 8;
        boff[u] = (brow * 136 + bseg * 8) * 2;
    }

    float acc[2][4][4] = {};
    const int NT = 16;

#pragma unroll
    for (int p = 0; p < 2; p++) {
#pragma unroll
        for (int u = 0; u < 2; u++) {
            cp16(sA + p * ASZ + aoff[u], aptr[u] + p * 64);
            cp16(sB + p * BSZ + boff[u], bptr[u] + (size_t)(p * 64) * DM);
        }
        cp_commit();
    }

    int slot = 0;
    for (int tt = 0; tt < NT; tt++) {
        cp_wait1();
        __syncthreads();

        if (tt + 2 < NT) {
            const int ps = (tt + 2) % 3;
            const int kt = (tt + 2) * 64;
#pragma unroll
            for (int u = 0; u < 2; u++) {
                cp16(sA + ps * ASZ + aoff[u], aptr[u] + kt);
                cp16(sB + ps * BSZ + boff[u], bptr[u] + (size_t)kt * DM);
            }
        }
        cp_commit();

        const uint32_t sAs = sA + slot * ASZ;
        const uint32_t sBs = sB + slot * BSZ;
#pragma unroll
        for (int ks = 0; ks < 4; ks++) {
            const int ko = ks * 16;
            uint32_t a[2][4], b[4][2];
#pragma unroll
            for (int mt = 0; mt < 2; mt++) ldsm4(a[mt], sAs + aoffm[mt] + ko * 2);
#pragma unroll
            for (int p = 0; p < 2; p++) {
                uint32_t r[4];
                ldsm4t(r, sBs + boffn[p] + ko * 136 * 2);
                b[p * 2][0] = r[0]; b[p * 2][1] = r[1];
                b[p * 2 + 1][0] = r[2]; b[p * 2 + 1][1] = r[3];
            }
#pragma unroll
            for (int mt = 0; mt < 2; mt++)
#pragma unroll
                for (int nt = 0; nt < 4; nt++) mma16(acc[mt][nt], a[mt], b[nt]);
        }
        slot = (slot + 1 == 3) ? 0 : slot + 1;
    }

#pragma unroll
    for (int mt = 0; mt < 2; mt++) {
        int r = row0 + wm * 32 + mt * 16 + gid;
#pragma unroll
        for (int nt = 0; nt < 4; nt++) {
            int col = col0 + wn * 32 + nt * 8 + 2 * tig;
            *(float2*)(out + (size_t)r * DM + col)       = make_float2(acc[mt][nt][0], acc[mt][nt][1]);
            *(float2*)(out + (size_t)(r + 8) * DM + col) = make_float2(acc[mt][nt][2], acc[mt][nt][3]);
        }
    }
}

// ---------------------------------------------------------------------------
extern "C" void kernel_launch(void* const* d_in, const int* in_sizes, int n_in,
                              void* d_out, int out_size)
{
    const float* q    = (const float*)d_in[0];
    const float* k    = (const float*)d_in[1];
    const float* v    = (const float*)d_in[2];
    const int*   mask = (const int*)  d_in[3];
    const float* Wq   = (const float*)d_in[4];
    const float* Wk   = (const float*)d_in[5];
    const float* Wv   = (const float*)d_in[6];
    const float* Wo   = (const float*)d_in[7];

    float* out = (float*)d_out;
    float* scp = out + (size_t)MR * DM;

    static int smem_set = 0;
    if (!smem_set) {
        cudaFuncSetAttribute(proj_mma,    cudaFuncAttributeMaxDynamicSharedMemorySize, 107520);
        cudaFuncSetAttribute(outproj_mma, cudaFuncAttributeMaxDynamicSharedMemorySize, 107520);
        cudaFuncSetAttribute(attn_mma,    cudaFuncAttributeMaxDynamicSharedMemorySize, 92160);
        smem_set = 1;
    }

    prep_all   <<<8704, 256>>>(q, k, v, Wq, Wk, Wv, Wo, mask);
    proj_mma   <<<dim3(32, 8, 3), 512, 107520>>>();
    attn_mma   <<<dim3(8, 64), 256, 92160>>>(scp);
    outproj_mma<<<dim3(32, 8), 512, 107520>>>(out);
}

// round 15
// speedup vs baseline: 1.1897x; 1.0165x over previous
#include <cuda_runtime.h>
#include <cuda_fp16.h>
#include <cstdint>

#define NH 16
#define NB 4
#define SQ 1024
#define DM 1024
#define DK 64
#define MR (NB * SQ)
#define HB (NH * NB)

// fp16 scratch (__device__ globals per allocation-free rule)
__device__ __half g_xq[(size_t)MR * DM];
__device__ __half g_xk[(size_t)MR * DM];
__device__ __half g_xv[(size_t)MR * DM];
__device__ __half g_wq[(size_t)NH * DM * DK];
__device__ __half g_wk[(size_t)NH * DM * DK];
__device__ __half g_wv[(size_t)NH * DM * DK];
__device__ __half g_wo[(size_t)DM * DM];
__device__ __half g_qh[(size_t)HB * SQ * DK];
__device__ __half g_kh[(size_t)HB * SQ * DK];
__device__ __half g_vh[(size_t)HB * SQ * DK];
__device__ __half g_ch[(size_t)MR * DM];
__device__ uint32_t g_mbits[(size_t)NB * SQ * (SQ / 32)];   // 1 bit per mask elem

__device__ __forceinline__ uint32_t h2u(__half2 h) { return *(uint32_t*)&h; }

__device__ __forceinline__ void ldsm4(uint32_t* r, uint32_t addr) {
    asm volatile("ldmatrix.sync.aligned.m8n8.x4.shared.b16 {%0,%1,%2,%3}, [%4];"
        : "=r"(r[0]), "=r"(r[1]), "=r"(r[2]), "=r"(r[3]) : "r"(addr));
}
__device__ __forceinline__ void ldsm4t(uint32_t* r, uint32_t addr) {
    asm volatile("ldmatrix.sync.aligned.m8n8.x4.trans.shared.b16 {%0,%1,%2,%3}, [%4];"
        : "=r"(r[0]), "=r"(r[1]), "=r"(r[2]), "=r"(r[3]) : "r"(addr));
}
__device__ __forceinline__ void mma16(float* d, const uint32_t* a, const uint32_t* b) {
    asm volatile("mma.sync.aligned.m16n8k16.row.col.f32.f16.f16.f32 "
        "{%0,%1,%2,%3}, {%4,%5,%6,%7}, {%8,%9}, {%0,%1,%2,%3};"
        : "+f"(d[0]), "+f"(d[1]), "+f"(d[2]), "+f"(d[3])
        : "r"(a[0]), "r"(a[1]), "r"(a[2]), "r"(a[3]), "r"(b[0]), "r"(b[1]));
}
__device__ __forceinline__ void cp16(uint32_t dst, const void* src) {
    asm volatile("cp.async.cg.shared.global [%0], [%1], 16;" :: "r"(dst), "l"(src));
}
__device__ __forceinline__ void cp_commit() { asm volatile("cp.async.commit_group;"); }
__device__ __forceinline__ void cp_wait0() { asm volatile("cp.async.wait_group 0;"); }
__device__ __forceinline__ void cp_wait1() { asm volatile("cp.async.wait_group 1;"); }

// ---------------------------------------------------------------------------
// Kernel 0: fused prep, 16 floats per thread (MLP=4).
// Blocks [0,3072): X fp32->fp16. [3072,4096): W. [4096,4352): mask bits.
// ---------------------------------------------------------------------------
__global__ __launch_bounds__(256) void prep_all(
    const float* __restrict__ q, const float* __restrict__ k, const float* __restrict__ v,
    const float* __restrict__ wq, const float* __restrict__ wk, const float* __restrict__ wv,
    const float* __restrict__ wo, const int* __restrict__ mask)
{
    const int bb = blockIdx.x;
    if (bb >= 4096) {                       // mask -> bits, 64 elems/thread
        int blk = bb - 4096;
        size_t tid = (size_t)blk * 256 + threadIdx.x;
        uint32_t w[2] = {0, 0};
#pragma unroll
        for (int half = 0; half < 2; half++) {
            size_t base = tid * 64 + half * 32;
            uint32_t bits = 0;
#pragma unroll
            for (int u = 0; u < 8; u++) {
                int4 m = *(const int4*)(mask + base + u * 4);
                bits |= (m.x ? 1u : 0u) << (u * 4 + 0);
                bits |= (m.y ? 1u : 0u) << (u * 4 + 1);
                bits |= (m.z ? 1u : 0u) << (u * 4 + 2);
                bits |= (m.w ? 1u : 0u) << (u * 4 + 3);
            }
            w[half] = bits;
        }
        *(uint2*)(g_mbits + tid * 2) = make_uint2(w[0], w[1]);
        return;
    }
    const float* src; __half* dst; int inner;
    if (bb < 3072) {
        int which = bb >> 10;
        src = (which == 0) ? q : (which == 1) ? k : v;
        dst = (which == 0) ? g_xq : (which == 1) ? g_xk : g_xv;
        inner = bb & 1023;
    } else {
        int which = (bb - 3072) >> 8;
        src = (which == 0) ? wq : (which == 1) ? wk : (which == 2) ? wv : wo;
        dst = (which == 0) ? g_wq : (which == 1) ? g_wk : (which == 2) ? g_wv : g_wo;
        inner = (bb - 3072) & 255;
    }
    size_t tid = (size_t)inner * 256 + threadIdx.x;
#pragma unroll
    for (int half = 0; half < 2; half++) {
        size_t i = tid * 2 + half;
        float4 a = ((const float4*)src)[i * 2];
        float4 b = ((const float4*)src)[i * 2 + 1];
        uint4 o;
        o.x = h2u(__floats2half2_rn(a.x, a.y));
        o.y = h2u(__floats2half2_rn(a.z, a.w));
        o.z = h2u(__floats2half2_rn(b.x, b.y));
        o.w = h2u(__floats2half2_rn(b.z, b.w));
        ((uint4*)dst)[i] = o;
    }
}

// ---------------------------------------------------------------------------
// Kernel 1: per-head projections. 512 threads (16 warps, 4x4), warp tile
// 32x32, BK=64, 3-stage cp.async ring. (at legacy-HMMA roofline; unchanged)
// ---------------------------------------------------------------------------
__global__ __launch_bounds__(512, 2) void proj_mma()
{
    const int which = blockIdx.z;
    const __half* X = (which == 0) ? g_xq : (which == 1) ? g_xk : g_xv;
    const __half* W = (which == 0) ? g_wq : (which == 1) ? g_wk : g_wv;
    __half* O       = (which == 0) ? g_qh : (which == 1) ? g_kh : g_vh;
    const int row0 = blockIdx.x * 128;
    const int col0 = blockIdx.y * 128;

    extern __shared__ __align__(16) __half sh[];
    __half* As = sh;                  // [3][128*72]
    __half* Bs = sh + 3 * 128 * 72;   // [3][64*136]
    const uint32_t sA = (uint32_t)__cvta_generic_to_shared(As);
    const uint32_t sB = (uint32_t)__cvta_generic_to_shared(Bs);
    const uint32_t ASZ = 128 * 72 * 2, BSZ = 64 * 136 * 2;

    const int t    = threadIdx.x;
    const int warp = t >> 5, lane = t & 31;
    const int gid  = lane >> 2, tig = lane & 3;
    const int wm   = warp >> 2;
    const int wn   = warp & 3;
    const int lr   = lane & 15;
    const int lc   = (lane >> 4) * 8;

    uint32_t aoffm[2], boffn[2];
#pragma unroll
    for (int mt = 0; mt < 2; mt++) aoffm[mt] = ((wm * 32 + mt * 16 + lr) * 72 + lc) * 2;
#pragma unroll
    for (int p = 0; p < 2; p++) boffn[p] = (lr * 136 + wn * 32 + p * 16 + lc) * 2;

    const __half* aptr[2]; uint32_t aoff[2];
    const __half* bptr[2]; uint32_t boff[2];
#pragma unroll
    for (int u = 0; u < 2; u++) {
        int c = t + u * 512;
        int arow = c >> 3, aseg = c & 7;
        aptr[u] = X + (size_t)(row0 + arow) * DM + aseg * 8;
        aoff[u] = (arow * 72 + aseg * 8) * 2;
        int brow = c >> 4, bseg = c & 15;
        int colh = col0 + bseg * 8, hh = colh >> 6, kk = colh & 63;
        bptr[u] = W + (size_t)hh * DM * DK + (size_t)brow * DK + kk;
        boff[u] = (brow * 136 + bseg * 8) * 2;
    }

    float acc[2][4][4] = {};
    const int NT = 16;

#pragma unroll
    for (int p = 0; p < 2; p++) {
#pragma unroll
        for (int u = 0; u < 2; u++) {
            cp16(sA + p * ASZ + aoff[u], aptr[u] + p * 64);
            cp16(sB + p * BSZ + boff[u], bptr[u] + (size_t)(p * 64) * DK);
        }
        cp_commit();
    }

    int slot = 0;
    for (int tt = 0; tt < NT; tt++) {
        cp_wait1();
        __syncthreads();

        if (tt + 2 < NT) {
            const int ps = (tt + 2) % 3;
            const int kt = (tt + 2) * 64;
#pragma unroll
            for (int u = 0; u < 2; u++) {
                cp16(sA + ps * ASZ + aoff[u], aptr[u] + kt);
                cp16(sB + ps * BSZ + boff[u], bptr[u] + (size_t)kt * DK);
            }
        }
        cp_commit();

        const uint32_t sAs = sA + slot * ASZ;
        const uint32_t sBs = sB + slot * BSZ;
#pragma unroll
        for (int ks = 0; ks < 4; ks++) {
            const int ko = ks * 16;
            uint32_t a[2][4], b[4][2];
#pragma unroll
            for (int mt = 0; mt < 2; mt++) ldsm4(a[mt], sAs + aoffm[mt] + ko * 2);
#pragma unroll
            for (int p = 0; p < 2; p++) {
                uint32_t r[4];
                ldsm4t(r, sBs + boffn[p] + ko * 136 * 2);
                b[p * 2][0] = r[0]; b[p * 2][1] = r[1];
                b[p * 2 + 1][0] = r[2]; b[p * 2 + 1][1] = r[3];
            }
#pragma unroll
            for (int mt = 0; mt < 2; mt++)
#pragma unroll
                for (int nt = 0; nt < 4; nt++) mma16(acc[mt][nt], a[mt], b[nt]);
        }
        slot = (slot + 1 == 3) ? 0 : slot + 1;
    }

#pragma unroll
    for (int mt = 0; mt < 2; mt++) {
        int r0 = row0 + wm * 32 + mt * 16 + gid;
        int bb = r0 >> 10, s0 = r0 & 1023;
#pragma unroll
        for (int nt = 0; nt < 4; nt++) {
            int col = col0 + wn * 32 + nt * 8 + 2 * tig;
            int hh = col >> 6, kk = col & 63;
            __half* base = O + (size_t)(hh * NB + bb) * SQ * DK;
            *(__half2*)(base + (size_t)s0 * DK + kk) =
                __floats2half2_rn(acc[mt][nt][0], acc[mt][nt][1]);
            *(__half2*)(base + (size_t)(s0 + 8) * DK + kk) =
                __floats2half2_rn(acc[mt][nt][2], acc[mt][nt][3]);
        }
    }
}

// ---------------------------------------------------------------------------
// Kernel 2: fused attention. NOW 256 q-rows per CTA (512 threads, 16 warps,
// 1 CTA/SM): K/V smem+gmem traffic per q-row HALVES. Register-resident P,
// 128-key outer tiles, bitmask, interleaved epilogue. Per-warp math identical
// to R14 (warp owns 16 q x all keys) -> bit-identical numerics.
// ---------------------------------------------------------------------------
__global__ __launch_bounds__(512, 1) void attn_mma(float* __restrict__ sc)
{
    extern __shared__ __align__(16) __half smh[];
    __half* Qs  = smh;                    // [256][72]
    __half* Ksm = Qs + 256 * 72;          // [2][128][72]
    __half* Vsm = Ksm + 2 * 128 * 72;     // [2][128][72]

    const uint32_t qsm = (uint32_t)__cvta_generic_to_shared(Qs);
    const uint32_t ksm = (uint32_t)__cvta_generic_to_shared(Ksm);
    const uint32_t vsm = (uint32_t)__cvta_generic_to_shared(Vsm);
    const uint32_t TSZ = 128 * 72 * 2;
    const uint32_t HSZ = 64 * 72 * 2;

    const int hb = blockIdx.y;
    const int h  = hb >> 2, b = hb & 3;
    const int q0 = blockIdx.x * 256;
    const int t = threadIdx.x, warp = t >> 5, lane = t & 31;
    const int gid = lane >> 2, tig = lane & 3;
    const int lr = lane & 15;
    const int lc = (lane >> 4) * 8;

    const __half* qbase = g_qh + ((size_t)hb * SQ + q0) * DK;
    const __half* kbase = g_kh + (size_t)hb * SQ * DK;
    const __half* vbase = g_vh + (size_t)hb * SQ * DK;

    const uint32_t qoff = ((warp * 16 + lr) * 72 + lc) * 2;
    uint32_t koff[4], voff[4];
#pragma unroll
    for (int p = 0; p < 4; p++) {
        koff[p] = ((p * 16 + ((lane >> 4) & 1) * 8 + (lane & 7)) * 72
                   + ((lane >> 3) & 1) * 8) * 2;
        voff[p] = (lr * 72 + p * 16 + lc) * 2;
    }

    // prologue: Q 256 rows (4 cp/thread) + K0/V0 128 rows (2+2 cp/thread)
#pragma unroll
    for (int u = 0; u < 4; u++) {
        int c = t + u * 512;
        int row = c >> 3, seg = c & 7;
        cp16(qsm + (row * 72 + seg * 8) * 2, qbase + (size_t)row * DK + seg * 8);
    }
#pragma unroll
    for (int u = 0; u < 2; u++) {
        int c = t + u * 512;
        int row = c >> 3, seg = c & 7;
        cp16(ksm + (row * 72 + seg * 8) * 2, kbase + (size_t)row * DK + seg * 8);
        cp16(vsm + (row * 72 + seg * 8) * 2, vbase + (size_t)row * DK + seg * 8);
    }
    cp_commit();
    cp_wait0();
    __syncthreads();

    uint32_t qf[4][4];
#pragma unroll
    for (int j = 0; j < 4; j++) ldsm4(qf[j], qsm + qoff + j * 16 * 2);

    float Oacc[8][4] = {};
    float rs0 = 0.f, rs1 = 0.f;
    const float NEGINF = __int_as_float(0xff800000u);

    const int rl0 = warp * 16 + gid;
    const int rl1 = rl0 + 8;
    const uint4* mb0 = (const uint4*)(g_mbits + ((size_t)b * SQ + q0 + rl0) * 32);
    const uint4* mb1 = (const uint4*)(g_mbits + ((size_t)b * SQ + q0 + rl1) * 32);
    float* srow0 = sc + ((size_t)hb * SQ + q0 + rl0) * SQ;
    float* srow1 = sc + ((size_t)hb * SQ + q0 + rl1) * SQ;

    for (int kb = 0; kb < 8; kb++) {
        const int slot = kb & 1;
        if (kb > 0) { cp_wait0(); __syncthreads(); }
        if (kb + 1 < 8) {
            const int so = slot ^ 1;
            const __half* kp = kbase + (size_t)(kb + 1) * 128 * DK;
            const __half* vp = vbase + (size_t)(kb + 1) * 128 * DK;
#pragma unroll
            for (int u = 0; u < 2; u++) {
                int c = t + u * 512;
                int row = c >> 3, seg = c & 7;
                cp16(ksm + so * TSZ + (row * 72 + seg * 8) * 2, kp + (size_t)row * DK + seg * 8);
                cp16(vsm + so * TSZ + (row * 72 + seg * 8) * 2, vp + (size_t)row * DK + seg * 8);
            }
        }
        cp_commit();

        uint4 w0v = mb0[kb];
        uint4 w1v = mb1[kb];
        uint32_t mw0[4] = {w0v.x, w0v.y, w0v.z, w0v.w};
        uint32_t mw1[4] = {w1v.x, w1v.y, w1v.z, w1v.w};

        const uint32_t Kp = ksm + slot * TSZ;
        const uint32_t Vp = vsm + slot * TSZ;

#pragma unroll
        for (int hf = 0; hf < 2; hf++) {
            const uint32_t Kph = Kp + hf * HSZ;
            const uint32_t Vph = Vp + hf * HSZ;

            // S = Q @ K^T : depth-2 pipelined over j
            float Sacc[8][4] = {};
            {
                uint32_t bk[2][8][2];
#pragma unroll
                for (int p = 0; p < 4; p++) {
                    uint32_t r[4];
                    ldsm4(r, Kph + koff[p]);
                    bk[0][p * 2][0] = r[0]; bk[0][p * 2][1] = r[1];
                    bk[0][p * 2 + 1][0] = r[2]; bk[0][p * 2 + 1][1] = r[3];
                }
#pragma unroll
                for (int j = 0; j < 4; j++) {
                    const int cur = j & 1, nxt = cur ^ 1;
                    if (j < 3) {
#pragma unroll
                        for (int p = 0; p < 4; p++) {
                            uint32_t r[4];
                            ldsm4(r, Kph + koff[p] + (j + 1) * 16 * 2);
                            bk[nxt][p * 2][0] = r[0]; bk[nxt][p * 2][1] = r[1];
                            bk[nxt][p * 2 + 1][0] = r[2]; bk[nxt][p * 2 + 1][1] = r[3];
                        }
                    }
#pragma unroll
                    for (int nt = 0; nt < 8; nt++) mma16(Sacc[nt], qf[j], bk[cur][nt]);
                }
            }

            // interleaved: epilogue for nt=2j,2j+1 -> apv, then PV mma step j
            const int cb = kb * 128 + hf * 64;
#pragma unroll
            for (int j = 0; j < 4; j++) {
                uint32_t apv[4];
#pragma unroll
                for (int e = 0; e < 2; e++) {
                    const int nt = 2 * j + e;
                    int cl = cb + nt * 8 + 2 * tig;
                    const int word = hf * 2 + (nt >> 2);
                    const int bit = (nt & 3) * 8 + 2 * tig;
                    uint32_t b0 = mw0[word] >> bit;
                    uint32_t b1 = mw1[word] >> bit;
                    float s00 = (b0 & 1u) ? Sacc[nt][0] * 0.125f : NEGINF;
                    float s01 = (b0 & 2u) ? Sacc[nt][1] * 0.125f : NEGINF;
                    float s10 = (b1 & 1u) ? Sacc[nt][2] * 0.125f : NEGINF;
                    float s11 = (b1 & 2u) ? Sacc[nt][3] * 0.125f : NEGINF;
                    __stcs((float2*)(srow0 + cl), make_float2(s00, s01));
                    __stcs((float2*)(srow1 + cl), make_float2(s10, s11));
                    float e00 = __expf(s00), e01 = __expf(s01);
                    float e10 = __expf(s10), e11 = __expf(s11);
                    rs0 += e00 + e01;
                    rs1 += e10 + e11;
                    if (e == 0) {
                        apv[0] = h2u(__floats2half2_rn(e00, e01));
                        apv[1] = h2u(__floats2half2_rn(e10, e11));
                    } else {
                        apv[2] = h2u(__floats2half2_rn(e00, e01));
                        apv[3] = h2u(__floats2half2_rn(e10, e11));
                    }
                }
                uint32_t bv[8][2];
#pragma unroll
                for (int p = 0; p < 4; p++) {
                    uint32_t r[4];
                    ldsm4t(r, Vph + voff[p] + j * 16 * 72 * 2);
                    bv[p * 2][0] = r[0]; bv[p * 2][1] = r[1];
                    bv[p * 2 + 1][0] = r[2]; bv[p * 2 + 1][1] = r[3];
                }
#pragma unroll
                for (int nt = 0; nt < 8; nt++) mma16(Oacc[nt], apv, bv[nt]);
            }
        }
    }

    rs0 += __shfl_xor_sync(0xffffffffu, rs0, 1);
    rs0 += __shfl_xor_sync(0xffffffffu, rs0, 2);
    rs1 += __shfl_xor_sync(0xffffffffu, rs1, 1);
    rs1 += __shfl_xor_sync(0xffffffffu, rs1, 2);
    float inv0 = 1.0f / rs0, inv1 = 1.0f / rs1;

    __half* c0 = g_ch + ((size_t)b * SQ + q0 + rl0) * DM + h * DK;
    __half* c1 = g_ch + ((size_t)b * SQ + q0 + rl1) * DM + h * DK;
#pragma unroll
    for (int nt = 0; nt < 8; nt++) {
        int cl = nt * 8 + 2 * tig;
        *(__half2*)(c0 + cl) = __floats2half2_rn(Oacc[nt][0] * inv0, Oacc[nt][1] * inv0);
        *(__half2*)(c1 + cl) = __floats2half2_rn(Oacc[nt][2] * inv1, Oacc[nt][3] * inv1);
    }
}

// ---------------------------------------------------------------------------
// Kernel 3: out = concat @ Wo. 512 threads, 4x4 warps, BK=64, 3-stage.
// (at legacy-HMMA roofline; unchanged)
// ---------------------------------------------------------------------------
__global__ __launch_bounds__(512, 2) void outproj_mma(float* __restrict__ out)
{
    const int row0 = blockIdx.x * 128;
    const int col0 = blockIdx.y * 128;

    extern __shared__ __align__(16) __half sh[];
    __half* As = sh;
    __half* Bs = sh + 3 * 128 * 72;
    const uint32_t sA = (uint32_t)__cvta_generic_to_shared(As);
    const uint32_t sB = (uint32_t)__cvta_generic_to_shared(Bs);
    const uint32_t ASZ = 128 * 72 * 2, BSZ = 64 * 136 * 2;

    const int t    = threadIdx.x;
    const int warp = t >> 5, lane = t & 31;
    const int gid  = lane >> 2, tig = lane & 3;
    const int wm   = warp >> 2;
    const int wn   = warp & 3;
    const int lr   = lane & 15;
    const int lc   = (lane >> 4) * 8;

    uint32_t aoffm[2], boffn[2];
#pragma unroll
    for (int mt = 0; mt < 2; mt++) aoffm[mt] = ((wm * 32 + mt * 16 + lr) * 72 + lc) * 2;
#pragma unroll
    for (int p = 0; p < 2; p++) boffn[p] = (lr * 136 + wn * 32 + p * 16 + lc) * 2;

    const __half* aptr[2]; uint32_t aoff[2];
    const __half* bptr[2]; uint32_t boff[2];
#pragma unroll
    for (int u = 0; u < 2; u++) {
        int c = t + u * 512;
        int arow = c >> 3, aseg = c & 7;
        aptr[u] = g_ch + (size_t)(row0 + arow) * DM + aseg * 8;
        aoff[u] = (arow * 72 + aseg * 8) * 2;
        int brow = c >> 4, bseg = c & 15;
        bptr[u] = g_wo + (size_t)brow * DM + col0 + bseg * 8;
        boff[u] = (brow * 136 + bseg * 8) * 2;
    }

    float acc[2][4][4] = {};
    const int NT = 16;

#pragma unroll
    for (int p = 0; p < 2; p++) {
#pragma unroll
        for (int u = 0; u < 2; u++) {
            cp16(sA + p * ASZ + aoff[u], aptr[u] + p * 64);
            cp16(sB + p * BSZ + boff[u], bptr[u] + (size_t)(p * 64) * DM);
        }
        cp_commit();
    }

    int slot = 0;
    for (int tt = 0; tt < NT; tt++) {
        cp_wait1();
        __syncthreads();

        if (tt + 2 < NT) {
            const int ps = (tt + 2) % 3;
            const int kt = (tt + 2) * 64;
#pragma unroll
            for (int u = 0; u < 2; u++) {
                cp16(sA + ps * ASZ + aoff[u], aptr[u] + kt);
                cp16(sB + ps * BSZ + boff[u], bptr[u] + (size_t)kt * DM);
            }
        }
        cp_commit();

        const uint32_t sAs = sA + slot * ASZ;
        const uint32_t sBs = sB + slot * BSZ;
#pragma unroll
        for (int ks = 0; ks < 4; ks++) {
            const int ko = ks * 16;
            uint32_t a[2][4], b[4][2];
#pragma unroll
            for (int mt = 0; mt < 2; mt++) ldsm4(a[mt], sAs + aoffm[mt] + ko * 2);
#pragma unroll
            for (int p = 0; p < 2; p++) {
                uint32_t r[4];
                ldsm4t(r, sBs + boffn[p] + ko * 136 * 2);
                b[p * 2][0] = r[0]; b[p * 2][1] = r[1];
                b[p * 2 + 1][0] = r[2]; b[p * 2 + 1][1] = r[3];
            }
#pragma unroll
            for (int mt = 0; mt < 2; mt++)
#pragma unroll
                for (int nt = 0; nt < 4; nt++) mma16(acc[mt][nt], a[mt], b[nt]);
        }
        slot = (slot + 1 == 3) ? 0 : slot + 1;
    }

#pragma unroll
    for (int mt = 0; mt < 2; mt++) {
        int r = row0 + wm * 32 + mt * 16 + gid;
#pragma unroll
        for (int nt = 0; nt < 4; nt++) {
            int col = col0 + wn * 32 + nt * 8 + 2 * tig;
            *(float2*)(out + (size_t)r * DM + col)       = make_float2(acc[mt][nt][0], acc[mt][nt][1]);
            *(float2*)(out + (size_t)(r + 8) * DM + col) = make_float2(acc[mt][nt][2], acc[mt][nt][3]);
        }
    }
}

// ---------------------------------------------------------------------------
extern "C" void kernel_launch(void* const* d_in, const int* in_sizes, int n_in,
                              void* d_out, int out_size)
{
    const float* q    = (const float*)d_in[0];
    const float* k    = (const float*)d_in[1];
    const float* v    = (const float*)d_in[2];
    const int*   mask = (const int*)  d_in[3];
    const float* Wq   = (const float*)d_in[4];
    const float* Wk   = (const float*)d_in[5];
    const float* Wv   = (const float*)d_in[6];
    const float* Wo   = (const float*)d_in[7];

    float* out = (float*)d_out;
    float* scp = out + (size_t)MR * DM;

    static int smem_set = 0;
    if (!smem_set) {
        cudaFuncSetAttribute(proj_mma,    cudaFuncAttributeMaxDynamicSharedMemorySize, 107520);
        cudaFuncSetAttribute(outproj_mma, cudaFuncAttributeMaxDynamicSharedMemorySize, 107520);
        cudaFuncSetAttribute(attn_mma,    cudaFuncAttributeMaxDynamicSharedMemorySize, 110592);
        smem_set = 1;
    }

    prep_all   <<<4352, 256>>>(q, k, v, Wq, Wk, Wv, Wo, mask);
    proj_mma   <<<dim3(32, 8, 3), 512, 107520>>>();
    attn_mma   <<<dim3(4, 64), 512, 110592>>>(scp);
    outproj_mma<<<dim3(32, 8), 512, 107520>>>(out);
}